// round 1
// baseline (speedup 1.0000x reference)
#include <cuda_runtime.h>
#include <math.h>

#define SS 4096
#define HH 1280
#define NHEAD 16
#define HDIM 80
#define IDIM 5120
#define EPSV 1e-6f

// ---------------- scratch (static device memory; no allocs allowed) --------
__device__ float g_ln  [(size_t)SS * HH];        // layernorm output
__device__ float g_qkv [(size_t)SS * 3 * HH];    // qkv projections
__device__ float g_attn[(size_t)NHEAD * SS * SS];// attention scores (1.07GB)
__device__ float g_ctx [(size_t)SS * HH];        // attention context
__device__ float g_x1  [(size_t)SS * HH];        // x after first residual
__device__ float g_ffn [(size_t)SS * IDIM];      // fc1 output

// ---------------- reductions ----------------------------------------------
__device__ __forceinline__ float block_reduce_sum(float v) {
    __shared__ float sh_sum[32];
    int lane = threadIdx.x & 31, wid = threadIdx.x >> 5;
    #pragma unroll
    for (int o = 16; o; o >>= 1) v += __shfl_xor_sync(0xffffffffu, v, o);
    if (lane == 0) sh_sum[wid] = v;
    __syncthreads();
    v = (threadIdx.x < (blockDim.x >> 5)) ? sh_sum[threadIdx.x] : 0.f;
    if (wid == 0) {
        #pragma unroll
        for (int o = 16; o; o >>= 1) v += __shfl_xor_sync(0xffffffffu, v, o);
        if (lane == 0) sh_sum[0] = v;
    }
    __syncthreads();
    float r = sh_sum[0];
    __syncthreads();
    return r;
}

__device__ __forceinline__ float block_reduce_max(float v) {
    __shared__ float sh_max[32];
    int lane = threadIdx.x & 31, wid = threadIdx.x >> 5;
    #pragma unroll
    for (int o = 16; o; o >>= 1) v = fmaxf(v, __shfl_xor_sync(0xffffffffu, v, o));
    if (lane == 0) sh_max[wid] = v;
    __syncthreads();
    v = (threadIdx.x < (blockDim.x >> 5)) ? sh_max[threadIdx.x] : -INFINITY;
    if (wid == 0) {
        #pragma unroll
        for (int o = 16; o; o >>= 1) v = fmaxf(v, __shfl_xor_sync(0xffffffffu, v, o));
        if (lane == 0) sh_max[0] = v;
    }
    __syncthreads();
    float r = sh_max[0];
    __syncthreads();
    return r;
}

// ---------------- layernorm -------------------------------------------------
// One block (256 threads) per row of 1280 = 5 elems/thread.
__global__ void ln_kernel(const float* __restrict__ x, const float* __restrict__ g,
                          const float* __restrict__ b, float* __restrict__ out) {
    int row = blockIdx.x;
    const float* xr = x + (size_t)row * HH;
    float v[5]; float s = 0.f;
    #pragma unroll
    for (int i = 0; i < 5; i++) { v[i] = xr[threadIdx.x + i * 256]; s += v[i]; }
    float mean = block_reduce_sum(s) * (1.f / HH);
    float vs = 0.f;
    #pragma unroll
    for (int i = 0; i < 5; i++) { float d = v[i] - mean; vs += d * d; }
    float var = block_reduce_sum(vs) * (1.f / HH);
    float inv = rsqrtf(var + EPSV);
    float* o = out + (size_t)row * HH;
    #pragma unroll
    for (int i = 0; i < 5; i++) {
        int c = threadIdx.x + i * 256;
        o[c] = (v[i] - mean) * inv * g[c] + b[c];
    }
}

// ---------------- RoPE ------------------------------------------------------
// One thread per (s, h, d<40) pair; rotates both q and k in place.
__global__ void rope_kernel(float* __restrict__ qkv, const float* __restrict__ cs,
                            const float* __restrict__ sn) {
    int idx = blockIdx.x * blockDim.x + threadIdx.x;
    if (idx >= SS * NHEAD * (HDIM / 2)) return;
    int d = idx % (HDIM / 2);
    int h = (idx / (HDIM / 2)) % NHEAD;
    int s = idx / ((HDIM / 2) * NHEAD);
    float c1 = cs[s * HDIM + d], c2 = cs[s * HDIM + d + 40];
    float s1 = sn[s * HDIM + d], s2 = sn[s * HDIM + d + 40];
    size_t base = (size_t)s * 3 * HH + h * HDIM;
    float* qp = qkv + base;
    float a = qp[d], bb = qp[d + 40];
    qp[d]      = a * c1 - bb * s1;
    qp[d + 40] = bb * c2 + a * s2;
    float* kp = qkv + base + HH;
    a = kp[d]; bb = kp[d + 40];
    kp[d]      = a * c1 - bb * s1;
    kp[d + 40] = bb * c2 + a * s2;
}

// ---------------- softmax ---------------------------------------------------
// One block per (q row, head). 4096 cols = 16/thread, kept in registers.
__global__ void softmax_kernel(float* __restrict__ attn, const float* __restrict__ mask) {
    int q = blockIdx.x, h = blockIdx.y;
    float* row = attn + ((size_t)h * SS + q) * SS;
    const float* mrow = mask + (size_t)q * SS;
    float v[16];
    float mx = -INFINITY;
    #pragma unroll
    for (int i = 0; i < 16; i++) {
        int c = threadIdx.x + i * 256;
        v[i] = row[c] + mrow[c];
        mx = fmaxf(mx, v[i]);
    }
    mx = block_reduce_max(mx);
    float s = 0.f;
    #pragma unroll
    for (int i = 0; i < 16; i++) { v[i] = __expf(v[i] - mx); s += v[i]; }
    s = block_reduce_sum(s);
    float inv = 1.f / s;
    #pragma unroll
    for (int i = 0; i < 16; i++) row[threadIdx.x + i * 256] = v[i] * inv;
}

// ---------------- GELU ------------------------------------------------------
__device__ __forceinline__ float gelu_tanh(float x) {
    return 0.5f * x * (1.f + tanhf(0.7978845608028654f * (x + 0.044715f * x * x * x)));
}

// ---------------- GEMM ------------------------------------------------------
// C[m,n] = alpha * sum_k A[m,k] * (BT ? B[n,k] : B[k,n])   (+bias, act, +residual)
// 128x128 tile, BK=8, 256 threads, 8x8 per-thread microtile, float4 loads.
// Assumes M % 128 == 0 and K % 8 == 0 (true for all call sites). N guarded.
template<bool BT, int ACT>
__global__ void __launch_bounds__(256)
gemm_kernel(const float* __restrict__ A, int lda, long long sA,
            const float* __restrict__ B, int ldb, long long sB,
            float* __restrict__ C, int ldc, long long sC,
            const float* __restrict__ bias,
            const float* __restrict__ Rsd, int ldr,
            int M, int N, int K, float alpha) {
    const int BM = 128, BN = 128, BK = 8;
    __shared__ float As[BK][BM];
    __shared__ float Bs[BK][BN];

    A += (size_t)blockIdx.z * sA;
    B += (size_t)blockIdx.z * sB;
    C += (size_t)blockIdx.z * sC;

    int bm = blockIdx.y * BM;
    int bn = blockIdx.x * BN;
    int tid = threadIdx.x;
    int tx = tid & 15, ty = tid >> 4;

    float acc[8][8];
    #pragma unroll
    for (int i = 0; i < 8; i++)
        #pragma unroll
        for (int j = 0; j < 8; j++) acc[i][j] = 0.f;

    int arow = tid >> 1;            // 0..127
    int acol = (tid & 1) * 4;       // 0 or 4

    for (int k0 = 0; k0 < K; k0 += BK) {
        // load A tile (128 x 8), one float4 per thread, store transposed
        float4 av = *(const float4*)(A + (size_t)(bm + arow) * lda + k0 + acol);
        As[acol + 0][arow] = av.x;
        As[acol + 1][arow] = av.y;
        As[acol + 2][arow] = av.z;
        As[acol + 3][arow] = av.w;

        if (BT) {
            // B is [N,K]: tile rows are n, cols are k
            int n = bn + arow;
            float4 bv = make_float4(0.f, 0.f, 0.f, 0.f);
            if (n < N) bv = *(const float4*)(B + (size_t)n * ldb + k0 + acol);
            Bs[acol + 0][arow] = bv.x;
            Bs[acol + 1][arow] = bv.y;
            Bs[acol + 2][arow] = bv.z;
            Bs[acol + 3][arow] = bv.w;
        } else {
            // B is [K,N]: tile rows are k (8), cols are n (128)
            int kk = k0 + (tid >> 5);
            int n = bn + (tid & 31) * 4;
            float4 bv = make_float4(0.f, 0.f, 0.f, 0.f);
            if (n + 3 < N) bv = *(const float4*)(B + (size_t)kk * ldb + n);
            *(float4*)&Bs[tid >> 5][(tid & 31) * 4] = bv;
        }
        __syncthreads();

        #pragma unroll
        for (int k = 0; k < BK; k++) {
            float4 a0 = *(const float4*)&As[k][ty * 8];
            float4 a1 = *(const float4*)&As[k][ty * 8 + 4];
            float4 b0 = *(const float4*)&Bs[k][tx * 8];
            float4 b1 = *(const float4*)&Bs[k][tx * 8 + 4];
            float ra[8] = {a0.x, a0.y, a0.z, a0.w, a1.x, a1.y, a1.z, a1.w};
            float rb[8] = {b0.x, b0.y, b0.z, b0.w, b1.x, b1.y, b1.z, b1.w};
            #pragma unroll
            for (int i = 0; i < 8; i++)
                #pragma unroll
                for (int j = 0; j < 8; j++) acc[i][j] += ra[i] * rb[j];
        }
        __syncthreads();
    }

    #pragma unroll
    for (int i = 0; i < 8; i++) {
        int row = bm + ty * 8 + i;
        #pragma unroll
        for (int j = 0; j < 8; j++) {
            int col = bn + tx * 8 + j;
            if (col < N) {
                float v = acc[i][j] * alpha;
                if (bias) v += bias[col];
                if (ACT == 1) v = gelu_tanh(v);
                if (Rsd) v += Rsd[(size_t)row * ldr + col];
                C[(size_t)row * ldc + col] = v;
            }
        }
    }
}

// ---------------- launch ----------------------------------------------------
extern "C" void kernel_launch(void* const* d_in, const int* in_sizes, int n_in,
                              void* d_out, int out_size) {
    const float* x      = (const float*)d_in[0];
    const float* mask   = (const float*)d_in[1];
    const float* cosp   = (const float*)d_in[2];
    const float* sinp   = (const float*)d_in[3];
    const float* qkv_w  = (const float*)d_in[4];
    const float* qkv_b  = (const float*)d_in[5];
    const float* proj_w = (const float*)d_in[6];
    const float* proj_b = (const float*)d_in[7];
    const float* fc1_w  = (const float*)d_in[8];
    const float* fc1_b  = (const float*)d_in[9];
    const float* fc2_w  = (const float*)d_in[10];
    const float* fc2_b  = (const float*)d_in[11];
    const float* ln1_g  = (const float*)d_in[12];
    const float* ln1_b  = (const float*)d_in[13];
    const float* ln2_g  = (const float*)d_in[14];
    const float* ln2_b  = (const float*)d_in[15];
    float* out = (float*)d_out;

    float *p_ln, *p_qkv, *p_attn, *p_ctx, *p_x1, *p_ffn;
    cudaGetSymbolAddress((void**)&p_ln,   g_ln);
    cudaGetSymbolAddress((void**)&p_qkv,  g_qkv);
    cudaGetSymbolAddress((void**)&p_attn, g_attn);
    cudaGetSymbolAddress((void**)&p_ctx,  g_ctx);
    cudaGetSymbolAddress((void**)&p_x1,   g_x1);
    cudaGetSymbolAddress((void**)&p_ffn,  g_ffn);

    // 1. LN1
    ln_kernel<<<SS, 256>>>(x, ln1_g, ln1_b, p_ln);

    // 2. QKV = ln @ qkv_w^T + qkv_b   (4096 x 3840 x 1280)
    gemm_kernel<true, 0><<<dim3(3840 / 128, SS / 128), 256>>>(
        p_ln, HH, 0, qkv_w, HH, 0, p_qkv, 3 * HH, 0,
        qkv_b, nullptr, 0, SS, 3 * HH, HH, 1.f);

    // 3. RoPE on q, k in place
    {
        int n = SS * NHEAD * (HDIM / 2);
        rope_kernel<<<(n + 255) / 256, 256>>>(p_qkv, cosp, sinp);
    }

    // 4. scores[h] = Q_h @ K_h^T * scaling   (batched over 16 heads)
    gemm_kernel<true, 0><<<dim3(SS / 128, SS / 128, NHEAD), 256>>>(
        p_qkv, 3 * HH, HDIM,                 // Q: base + h*80, row stride 3840
        p_qkv + HH, 3 * HH, HDIM,            // K
        p_attn, SS, (long long)SS * SS,
        nullptr, nullptr, 0, SS, SS, HDIM, rsqrtf((float)HDIM));

    // 5. softmax(+mask) per (q,h) row
    softmax_kernel<<<dim3(SS, NHEAD), 256>>>(p_attn, mask);

    // 6. ctx[h] = attn_h @ V_h   (M=4096, N=80, K=4096)
    gemm_kernel<false, 0><<<dim3(1, SS / 128, NHEAD), 256>>>(
        p_attn, SS, (long long)SS * SS,
        p_qkv + 2 * HH, 3 * HH, HDIM,        // V: [k, d], row stride 3840
        p_ctx, HH, HDIM,
        nullptr, nullptr, 0, SS, HDIM, SS, 1.f);

    // 7. x1 = x + ctx @ proj_w^T + proj_b
    gemm_kernel<true, 0><<<dim3(HH / 128, SS / 128), 256>>>(
        p_ctx, HH, 0, proj_w, HH, 0, p_x1, HH, 0,
        proj_b, x, HH, SS, HH, HH, 1.f);

    // 8. LN2
    ln_kernel<<<SS, 256>>>(p_x1, ln2_g, ln2_b, p_ln);

    // 9. ffn = gelu(ln @ fc1_w^T + fc1_b)   (4096 x 5120 x 1280)
    gemm_kernel<true, 1><<<dim3(IDIM / 128, SS / 128), 256>>>(
        p_ln, HH, 0, fc1_w, HH, 0, p_ffn, IDIM, 0,
        fc1_b, nullptr, 0, SS, IDIM, HH, 1.f);

    // 10. out = x1 + ffn @ fc2_w^T + fc2_b   (4096 x 1280 x 5120)
    gemm_kernel<true, 0><<<dim3(HH / 128, SS / 128), 256>>>(
        p_ffn, IDIM, 0, fc2_w, IDIM, 0, out, HH, 0,
        fc2_b, p_x1, HH, SS, HH, IDIM, 1.f);
}

// round 4
// speedup vs baseline: 1.8916x; 1.8916x over previous
#include <cuda_runtime.h>
#include <math.h>
#include <stdint.h>

#define SS 4096
#define HH 1280
#define NHEAD 16
#define HDIM 80
#define IDIM 5120
#define EPSV 1e-6f

// ---------------- scratch (static device memory; no allocs allowed) --------
__device__ float g_ln  [(size_t)SS * HH];
__device__ float g_qkv [(size_t)SS * 3 * HH];
__device__ float g_attn[(size_t)NHEAD * SS * SS];
__device__ float g_ctx [(size_t)SS * HH];
__device__ float g_x1  [(size_t)SS * HH];
__device__ float g_ffn [(size_t)SS * IDIM];

// ---------------- helpers ---------------------------------------------------
__device__ __forceinline__ float to_tf32(float x) {
    float r;
    asm("cvt.rna.tf32.f32 %0, %1;" : "=f"(r) : "f"(x));
    return r;
}
__device__ __forceinline__ float4 cvt4(float4 v) {
    v.x = to_tf32(v.x); v.y = to_tf32(v.y); v.z = to_tf32(v.z); v.w = to_tf32(v.w);
    return v;
}
__device__ __forceinline__ void mma_tf32(float* d, uint32_t a0, uint32_t a1,
                                         uint32_t a2, uint32_t a3,
                                         uint32_t b0, uint32_t b1) {
    asm volatile(
        "mma.sync.aligned.m16n8k8.row.col.f32.tf32.tf32.f32 "
        "{%0,%1,%2,%3}, {%4,%5,%6,%7}, {%8,%9}, {%0,%1,%2,%3};"
        : "+f"(d[0]), "+f"(d[1]), "+f"(d[2]), "+f"(d[3])
        : "r"(a0), "r"(a1), "r"(a2), "r"(a3), "r"(b0), "r"(b1));
}

// ---------------- reductions ----------------------------------------------
__device__ __forceinline__ float block_reduce_sum(float v) {
    __shared__ float sh_sum[32];
    int lane = threadIdx.x & 31, wid = threadIdx.x >> 5;
    #pragma unroll
    for (int o = 16; o; o >>= 1) v += __shfl_xor_sync(0xffffffffu, v, o);
    if (lane == 0) sh_sum[wid] = v;
    __syncthreads();
    v = (threadIdx.x < (blockDim.x >> 5)) ? sh_sum[threadIdx.x] : 0.f;
    if (wid == 0) {
        #pragma unroll
        for (int o = 16; o; o >>= 1) v += __shfl_xor_sync(0xffffffffu, v, o);
        if (lane == 0) sh_sum[0] = v;
    }
    __syncthreads();
    float r = sh_sum[0];
    __syncthreads();
    return r;
}
__device__ __forceinline__ float block_reduce_max(float v) {
    __shared__ float sh_max[32];
    int lane = threadIdx.x & 31, wid = threadIdx.x >> 5;
    #pragma unroll
    for (int o = 16; o; o >>= 1) v = fmaxf(v, __shfl_xor_sync(0xffffffffu, v, o));
    if (lane == 0) sh_max[wid] = v;
    __syncthreads();
    v = (threadIdx.x < (blockDim.x >> 5)) ? sh_max[threadIdx.x] : -INFINITY;
    if (wid == 0) {
        #pragma unroll
        for (int o = 16; o; o >>= 1) v = fmaxf(v, __shfl_xor_sync(0xffffffffu, v, o));
        if (lane == 0) sh_max[0] = v;
    }
    __syncthreads();
    float r = sh_max[0];
    __syncthreads();
    return r;
}

// ---------------- layernorm -------------------------------------------------
__global__ void ln_kernel(const float* __restrict__ x, const float* __restrict__ g,
                          const float* __restrict__ b, float* __restrict__ out) {
    int row = blockIdx.x;
    const float* xr = x + (size_t)row * HH;
    float v[5]; float s = 0.f;
    #pragma unroll
    for (int i = 0; i < 5; i++) { v[i] = xr[threadIdx.x + i * 256]; s += v[i]; }
    float mean = block_reduce_sum(s) * (1.f / HH);
    float vs = 0.f;
    #pragma unroll
    for (int i = 0; i < 5; i++) { float d = v[i] - mean; vs += d * d; }
    float var = block_reduce_sum(vs) * (1.f / HH);
    float inv = rsqrtf(var + EPSV);
    float* o = out + (size_t)row * HH;
    #pragma unroll
    for (int i = 0; i < 5; i++) {
        int c = threadIdx.x + i * 256;
        o[c] = (v[i] - mean) * inv * g[c] + b[c];
    }
}

// ---------------- RoPE ------------------------------------------------------
__global__ void rope_kernel(float* __restrict__ qkv, const float* __restrict__ cs,
                            const float* __restrict__ sn) {
    int idx = blockIdx.x * blockDim.x + threadIdx.x;
    if (idx >= SS * NHEAD * (HDIM / 2)) return;
    int d = idx % (HDIM / 2);
    int h = (idx / (HDIM / 2)) % NHEAD;
    int s = idx / ((HDIM / 2) * NHEAD);
    float c1 = cs[s * HDIM + d], c2 = cs[s * HDIM + d + 40];
    float s1 = sn[s * HDIM + d], s2 = sn[s * HDIM + d + 40];
    size_t base = (size_t)s * 3 * HH + h * HDIM;
    float* qp = qkv + base;
    float a = qp[d], bb = qp[d + 40];
    qp[d]      = a * c1 - bb * s1;
    qp[d + 40] = bb * c2 + a * s2;
    float* kp = qkv + base + HH;
    a = kp[d]; bb = kp[d + 40];
    kp[d]      = a * c1 - bb * s1;
    kp[d + 40] = bb * c2 + a * s2;
}

// ---------------- softmax ---------------------------------------------------
__global__ void softmax_kernel(float* __restrict__ attn, const float* __restrict__ mask) {
    int q = blockIdx.x, h = blockIdx.y;
    float* row = attn + ((size_t)h * SS + q) * SS;
    const float* mrow = mask + (size_t)q * SS;
    float v[16];
    float mx = -INFINITY;
    #pragma unroll
    for (int i = 0; i < 16; i++) {
        int c = threadIdx.x + i * 256;
        v[i] = row[c] + mrow[c];
        mx = fmaxf(mx, v[i]);
    }
    mx = block_reduce_max(mx);
    float s = 0.f;
    #pragma unroll
    for (int i = 0; i < 16; i++) { v[i] = __expf(v[i] - mx); s += v[i]; }
    s = block_reduce_sum(s);
    float inv = 1.f / s;
    #pragma unroll
    for (int i = 0; i < 16; i++) row[threadIdx.x + i * 256] = v[i] * inv;
}

__device__ __forceinline__ float gelu_tanh(float x) {
    return 0.5f * x * (1.f + tanhf(0.7978845608028654f * (x + 0.044715f * x * x * x)));
}

// ================= TF32 mma.sync GEMM =======================================
// C[m,n] = alpha * sum_k A[m,k] * B'[n,k]  (+bias, act, +residual)
//   BMODE 0: B is [N,K] row-major (K contiguous)  -> B' = B
//   BMODE 1: B is [K,N] row-major (N contiguous)  -> B'[n,k] = B[k,n]
// CTA tile 128x128xBK16, 256 threads = 8 warps (4m x 2n), warp tile 32x64.
// Requires M % 128 == 0 and K % 16 == 0 (all call sites satisfy).
template<int BMODE, int ACT>
__global__ void __launch_bounds__(256)
mma_gemm(const float* __restrict__ A, int lda, long long sA,
         const float* __restrict__ B, int ldb, long long sB,
         float* __restrict__ C, int ldc, long long sC,
         const float* __restrict__ bias,
         const float* __restrict__ Rsd, int ldr,
         int N, int K, float alpha) {
    __shared__ float As[2][16][132];
    __shared__ float Bs[2][16][132];

    A += (size_t)blockIdx.z * sA;
    B += (size_t)blockIdx.z * sB;
    C += (size_t)blockIdx.z * sC;

    const int tid = threadIdx.x;
    const int wid = tid >> 5;
    const int lane = tid & 31;
    const int warpM = (wid >> 1) * 32;     // 0,32,64,96
    const int warpN = (wid & 1) * 64;      // 0,64
    const int bm = blockIdx.y * 128;
    const int bn = blockIdx.x * 128;

    float acc[2][8][4];
    #pragma unroll
    for (int i = 0; i < 2; i++)
        #pragma unroll
        for (int j = 0; j < 8; j++)
            #pragma unroll
            for (int q = 0; q < 4; q++) acc[i][j][q] = 0.f;

    const int arow = tid >> 1;             // 0..127
    const int acol = (tid & 1) * 8;        // 0 or 8

    auto load_stage = [&](int k0, int buf) {
        // A tile: 128 x 16, thread loads 2 float4 from one row, stores transposed
        {
            const float* ar = A + (size_t)(bm + arow) * lda + k0 + acol;
            float4 v0 = cvt4(*(const float4*)(ar));
            float4 v1 = cvt4(*(const float4*)(ar + 4));
            As[buf][acol + 0][arow] = v0.x; As[buf][acol + 1][arow] = v0.y;
            As[buf][acol + 2][arow] = v0.z; As[buf][acol + 3][arow] = v0.w;
            As[buf][acol + 4][arow] = v1.x; As[buf][acol + 5][arow] = v1.y;
            As[buf][acol + 6][arow] = v1.z; As[buf][acol + 7][arow] = v1.w;
        }
        if (BMODE == 0) {
            int n = bn + arow;
            const float* br = B + (size_t)n * ldb + k0 + acol;
            float4 v0 = make_float4(0.f,0.f,0.f,0.f), v1 = v0;
            if (n < N) { v0 = cvt4(*(const float4*)(br)); v1 = cvt4(*(const float4*)(br + 4)); }
            Bs[buf][acol + 0][arow] = v0.x; Bs[buf][acol + 1][arow] = v0.y;
            Bs[buf][acol + 2][arow] = v0.z; Bs[buf][acol + 3][arow] = v0.w;
            Bs[buf][acol + 4][arow] = v1.x; Bs[buf][acol + 5][arow] = v1.y;
            Bs[buf][acol + 6][arow] = v1.z; Bs[buf][acol + 7][arow] = v1.w;
        } else {
            // B[K,N]: row k = tid>>4 (16 rows), n = (tid&15)*8, contiguous copy
            int kk = tid >> 4;
            int nc = (tid & 15) * 8;
            const float* br = B + (size_t)(k0 + kk) * ldb + bn + nc;
            float4 v0 = make_float4(0.f,0.f,0.f,0.f), v1 = v0;
            if (bn + nc + 4 <= N) v0 = cvt4(*(const float4*)(br));
            if (bn + nc + 8 <= N) v1 = cvt4(*(const float4*)(br + 4));
            *(float4*)&Bs[buf][kk][nc]     = v0;
            *(float4*)&Bs[buf][kk][nc + 4] = v1;
        }
    };

    auto compute_stage = [&](int buf) {
        #pragma unroll
        for (int kk = 0; kk < 16; kk += 8) {
            uint32_t af[2][4], bf[8][2];
            const int kl = kk + (lane & 3);
            const int g4 = lane >> 2;
            #pragma unroll
            for (int mt = 0; mt < 2; mt++) {
                int m = warpM + mt * 16 + g4;
                af[mt][0] = __float_as_uint(As[buf][kl][m]);
                af[mt][1] = __float_as_uint(As[buf][kl][m + 8]);
                af[mt][2] = __float_as_uint(As[buf][kl + 4][m]);
                af[mt][3] = __float_as_uint(As[buf][kl + 4][m + 8]);
            }
            #pragma unroll
            for (int nt = 0; nt < 8; nt++) {
                int n = warpN + nt * 8 + g4;
                bf[nt][0] = __float_as_uint(Bs[buf][kl][n]);
                bf[nt][1] = __float_as_uint(Bs[buf][kl + 4][n]);
            }
            #pragma unroll
            for (int mt = 0; mt < 2; mt++)
                #pragma unroll
                for (int nt = 0; nt < 8; nt++)
                    mma_tf32(acc[mt][nt], af[mt][0], af[mt][1], af[mt][2], af[mt][3],
                             bf[nt][0], bf[nt][1]);
        }
    };

    const int nst = K / 16;
    load_stage(0, 0);
    __syncthreads();
    for (int s = 0; s < nst; s++) {
        if (s + 1 < nst) load_stage((s + 1) * 16, (s + 1) & 1);
        compute_stage(s & 1);
        __syncthreads();
    }

    // ---- epilogue ----
    #pragma unroll
    for (int mt = 0; mt < 2; mt++) {
        #pragma unroll
        for (int rr = 0; rr < 2; rr++) {
            int row = bm + warpM + mt * 16 + (lane >> 2) + rr * 8;
            float* Crow = C + (size_t)row * ldc;
            const float* Rrow = Rsd ? (Rsd + (size_t)row * ldr) : nullptr;
            #pragma unroll
            for (int nt = 0; nt < 8; nt++) {
                int col = bn + warpN + nt * 8 + (lane & 3) * 2;
                if (col < N) {
                    float v0 = acc[mt][nt][rr * 2 + 0] * alpha;
                    float v1 = acc[mt][nt][rr * 2 + 1] * alpha;
                    if (bias) { v0 += bias[col]; v1 += bias[col + 1]; }
                    if (ACT == 1) { v0 = gelu_tanh(v0); v1 = gelu_tanh(v1); }
                    if (Rrow) { v0 += Rrow[col]; v1 += Rrow[col + 1]; }
                    *(float2*)(Crow + col) = make_float2(v0, v1);
                }
            }
        }
    }
}

// ---------------- launch ----------------------------------------------------
extern "C" void kernel_launch(void* const* d_in, const int* in_sizes, int n_in,
                              void* d_out, int out_size) {
    const float* x      = (const float*)d_in[0];
    const float* mask   = (const float*)d_in[1];
    const float* cosp   = (const float*)d_in[2];
    const float* sinp   = (const float*)d_in[3];
    const float* qkv_w  = (const float*)d_in[4];
    const float* qkv_b  = (const float*)d_in[5];
    const float* proj_w = (const float*)d_in[6];
    const float* proj_b = (const float*)d_in[7];
    const float* fc1_w  = (const float*)d_in[8];
    const float* fc1_b  = (const float*)d_in[9];
    const float* fc2_w  = (const float*)d_in[10];
    const float* fc2_b  = (const float*)d_in[11];
    const float* ln1_g  = (const float*)d_in[12];
    const float* ln1_b  = (const float*)d_in[13];
    const float* ln2_g  = (const float*)d_in[14];
    const float* ln2_b  = (const float*)d_in[15];
    float* out = (float*)d_out;

    float *p_ln, *p_qkv, *p_attn, *p_ctx, *p_x1, *p_ffn;
    cudaGetSymbolAddress((void**)&p_ln,   g_ln);
    cudaGetSymbolAddress((void**)&p_qkv,  g_qkv);
    cudaGetSymbolAddress((void**)&p_attn, g_attn);
    cudaGetSymbolAddress((void**)&p_ctx,  g_ctx);
    cudaGetSymbolAddress((void**)&p_x1,   g_x1);
    cudaGetSymbolAddress((void**)&p_ffn,  g_ffn);

    // 1. LN1
    ln_kernel<<<SS, 256>>>(x, ln1_g, ln1_b, p_ln);

    // 2. QKV = ln @ qkv_w^T + qkv_b   (4096 x 3840 x 1280)
    mma_gemm<0, 0><<<dim3(3840 / 128, SS / 128), 256>>>(
        p_ln, HH, 0, qkv_w, HH, 0, p_qkv, 3 * HH, 0,
        qkv_b, nullptr, 0, 3 * HH, HH, 1.f);

    // 3. RoPE on q, k in place
    {
        int n = SS * NHEAD * (HDIM / 2);
        rope_kernel<<<(n + 255) / 256, 256>>>(p_qkv, cosp, sinp);
    }

    // 4. scores[h] = Q_h @ K_h^T * scaling   (batched over 16 heads)
    mma_gemm<0, 0><<<dim3(SS / 128, SS / 128, NHEAD), 256>>>(
        p_qkv, 3 * HH, HDIM,
        p_qkv + HH, 3 * HH, HDIM,
        p_attn, SS, (long long)SS * SS,
        nullptr, nullptr, 0, SS, HDIM, rsqrtf((float)HDIM));

    // 5. softmax(+mask)
    softmax_kernel<<<dim3(SS, NHEAD), 256>>>(p_attn, mask);

    // 6. ctx[h] = attn_h @ V_h   (M=4096, N=80, K=4096)
    mma_gemm<1, 0><<<dim3(1, SS / 128, NHEAD), 256>>>(
        p_attn, SS, (long long)SS * SS,
        p_qkv + 2 * HH, 3 * HH, HDIM,
        p_ctx, HH, HDIM,
        nullptr, nullptr, 0, HDIM, SS, 1.f);

    // 7. x1 = x + ctx @ proj_w^T + proj_b
    mma_gemm<0, 0><<<dim3(HH / 128, SS / 128), 256>>>(
        p_ctx, HH, 0, proj_w, HH, 0, p_x1, HH, 0,
        proj_b, x, HH, HH, HH, 1.f);

    // 8. LN2
    ln_kernel<<<SS, 256>>>(p_x1, ln2_g, ln2_b, p_ln);

    // 9. ffn = gelu(ln @ fc1_w^T + fc1_b)
    mma_gemm<0, 1><<<dim3(IDIM / 128, SS / 128), 256>>>(
        p_ln, HH, 0, fc1_w, HH, 0, p_ffn, IDIM, 0,
        fc1_b, nullptr, 0, IDIM, HH, 1.f);

    // 10. out = x1 + ffn @ fc2_w^T + fc2_b
    mma_gemm<0, 0><<<dim3(HH / 128, SS / 128), 256>>>(
        p_ffn, IDIM, 0, fc2_w, IDIM, 0, out, HH, 0,
        fc2_b, p_x1, HH, HH, IDIM, 1.f);
}

// round 6
// speedup vs baseline: 2.3885x; 1.2627x over previous
#include <cuda_runtime.h>
#include <math.h>
#include <stdint.h>

#define SS 4096
#define HH 1280
#define NHEAD 16
#define HDIM 80
#define IDIM 5120
#define EPSV 1e-6f

// ---------------- scratch (static device memory; no allocs allowed) --------
__device__ float g_ln  [(size_t)SS * HH];
__device__ float g_qkv [(size_t)SS * 3 * HH];
__device__ float g_attn[(size_t)NHEAD * SS * SS];
__device__ float g_ctx [(size_t)SS * HH];
__device__ float g_x1  [(size_t)SS * HH];
__device__ float g_ffn [(size_t)SS * IDIM];

// ---------------- helpers ---------------------------------------------------
__device__ __forceinline__ float to_tf32(float x) {
    float r;
    asm("cvt.rna.tf32.f32 %0, %1;" : "=f"(r) : "f"(x));
    return r;
}
__device__ __forceinline__ float4 cvt4(float4 v) {
    v.x = to_tf32(v.x); v.y = to_tf32(v.y); v.z = to_tf32(v.z); v.w = to_tf32(v.w);
    return v;
}
__device__ __forceinline__ void mma_tf32(float* d, uint32_t a0, uint32_t a1,
                                         uint32_t a2, uint32_t a3,
                                         uint32_t b0, uint32_t b1) {
    asm volatile(
        "mma.sync.aligned.m16n8k8.row.col.f32.tf32.tf32.f32 "
        "{%0,%1,%2,%3}, {%4,%5,%6,%7}, {%8,%9}, {%0,%1,%2,%3};"
        : "+f"(d[0]), "+f"(d[1]), "+f"(d[2]), "+f"(d[3])
        : "r"(a0), "r"(a1), "r"(a2), "r"(a3), "r"(b0), "r"(b1));
}

// ---------------- reductions ----------------------------------------------
__device__ __forceinline__ float block_reduce_sum(float v) {
    __shared__ float sh_sum[32];
    int lane = threadIdx.x & 31, wid = threadIdx.x >> 5;
    #pragma unroll
    for (int o = 16; o; o >>= 1) v += __shfl_xor_sync(0xffffffffu, v, o);
    if (lane == 0) sh_sum[wid] = v;
    __syncthreads();
    v = (threadIdx.x < (blockDim.x >> 5)) ? sh_sum[threadIdx.x] : 0.f;
    if (wid == 0) {
        #pragma unroll
        for (int o = 16; o; o >>= 1) v += __shfl_xor_sync(0xffffffffu, v, o);
        if (lane == 0) sh_sum[0] = v;
    }
    __syncthreads();
    float r = sh_sum[0];
    __syncthreads();
    return r;
}
__device__ __forceinline__ float block_reduce_max(float v) {
    __shared__ float sh_max[32];
    int lane = threadIdx.x & 31, wid = threadIdx.x >> 5;
    #pragma unroll
    for (int o = 16; o; o >>= 1) v = fmaxf(v, __shfl_xor_sync(0xffffffffu, v, o));
    if (lane == 0) sh_max[wid] = v;
    __syncthreads();
    v = (threadIdx.x < (blockDim.x >> 5)) ? sh_max[threadIdx.x] : -INFINITY;
    if (wid == 0) {
        #pragma unroll
        for (int o = 16; o; o >>= 1) v = fmaxf(v, __shfl_xor_sync(0xffffffffu, v, o));
        if (lane == 0) sh_max[0] = v;
    }
    __syncthreads();
    float r = sh_max[0];
    __syncthreads();
    return r;
}

// ---------------- layernorm -------------------------------------------------
__global__ void ln_kernel(const float* __restrict__ x, const float* __restrict__ g,
                          const float* __restrict__ b, float* __restrict__ out) {
    int row = blockIdx.x;
    const float* xr = x + (size_t)row * HH;
    float v[5]; float s = 0.f;
    #pragma unroll
    for (int i = 0; i < 5; i++) { v[i] = xr[threadIdx.x + i * 256]; s += v[i]; }
    float mean = block_reduce_sum(s) * (1.f / HH);
    float vs = 0.f;
    #pragma unroll
    for (int i = 0; i < 5; i++) { float d = v[i] - mean; vs += d * d; }
    float var = block_reduce_sum(vs) * (1.f / HH);
    float inv = rsqrtf(var + EPSV);
    float* o = out + (size_t)row * HH;
    #pragma unroll
    for (int i = 0; i < 5; i++) {
        int c = threadIdx.x + i * 256;
        o[c] = (v[i] - mean) * inv * g[c] + b[c];
    }
}

// ---------------- RoPE ------------------------------------------------------
__global__ void rope_kernel(float* __restrict__ qkv, const float* __restrict__ cs,
                            const float* __restrict__ sn) {
    int idx = blockIdx.x * blockDim.x + threadIdx.x;
    if (idx >= SS * NHEAD * (HDIM / 2)) return;
    int d = idx % (HDIM / 2);
    int h = (idx / (HDIM / 2)) % NHEAD;
    int s = idx / ((HDIM / 2) * NHEAD);
    float c1 = cs[s * HDIM + d], c2 = cs[s * HDIM + d + 40];
    float s1 = sn[s * HDIM + d], s2 = sn[s * HDIM + d + 40];
    size_t base = (size_t)s * 3 * HH + h * HDIM;
    float* qp = qkv + base;
    float a = qp[d], bb = qp[d + 40];
    qp[d]      = a * c1 - bb * s1;
    qp[d + 40] = bb * c2 + a * s2;
    float* kp = qkv + base + HH;
    a = kp[d]; bb = kp[d + 40];
    kp[d]      = a * c1 - bb * s1;
    kp[d + 40] = bb * c2 + a * s2;
}

// ---------------- softmax ---------------------------------------------------
__global__ void softmax_kernel(float* __restrict__ attn, const float* __restrict__ mask) {
    int q = blockIdx.x, h = blockIdx.y;
    float* row = attn + ((size_t)h * SS + q) * SS;
    const float* mrow = mask + (size_t)q * SS;
    float v[16];
    float mx = -INFINITY;
    #pragma unroll
    for (int i = 0; i < 16; i++) {
        int c = threadIdx.x + i * 256;
        v[i] = row[c] + mrow[c];
        mx = fmaxf(mx, v[i]);
    }
    mx = block_reduce_max(mx);
    float s = 0.f;
    #pragma unroll
    for (int i = 0; i < 16; i++) { v[i] = __expf(v[i] - mx); s += v[i]; }
    s = block_reduce_sum(s);
    float inv = 1.f / s;
    #pragma unroll
    for (int i = 0; i < 16; i++) row[threadIdx.x + i * 256] = v[i] * inv;
}

__device__ __forceinline__ float gelu_tanh(float x) {
    return 0.5f * x * (1.f + tanhf(0.7978845608028654f * (x + 0.044715f * x * x * x)));
}

// ================= TF32 mma.sync GEMM, v2 ===================================
// C[m,n] = alpha * sum_k A[m,k] * B'[n,k]  (+bias, act, +residual)
//   BMODE 0: B is [N,K] row-major  -> B tile stored [n][k] swizzled
//   BMODE 1: B is [K,N] row-major  -> B tile stored [k][n] padded (no transpose)
// CTA tile 128x128x32, 256 threads = 8 warps (4m x 2n), warp tile 32x64.
// SMEM rows = 32 floats (128B); chunk-XOR swizzle chunk' = chunk ^ (row&7)
// makes all fragment LDS conflict-free. Register-prefetch pipeline: LDG of
// stage s+1 issued before compute of stage s; STS after; one sync per stage.
// Requires M % 128 == 0. BMODE0 additionally N % 128 == 0 (all call sites OK).
template<int BMODE, int ACT>
__global__ void __launch_bounds__(256)
mma_gemm(const float* __restrict__ A, int lda, long long sA,
         const float* __restrict__ B, int ldb, long long sB,
         float* __restrict__ C, int ldc, long long sC,
         const float* __restrict__ bias,
         const float* __restrict__ Rsd, int ldr,
         int N, int K, float alpha) {
    constexpr int BK = 32;

    extern __shared__ char smem_raw[];
    // As: 2 x 128 x 32 floats (32KB) at offset 0
    float (*As)[128][32] = (float (*)[128][32])(smem_raw);
    // BMODE0: Bs0: 2 x 128 x 32  | BMODE1: Bs1: 2 x 32 x 136
    float (*Bs0)[128][32] = (float (*)[128][32])(smem_raw + 32768);
    float (*Bs1)[32][136] = (float (*)[32][136])(smem_raw + 32768);

    A += (size_t)blockIdx.z * sA;
    B += (size_t)blockIdx.z * sB;
    C += (size_t)blockIdx.z * sC;

    const int tid = threadIdx.x;
    const int wid = tid >> 5;
    const int lane = tid & 31;
    const int kl = lane & 3;
    const int g4 = lane >> 2;
    const int warpM = (wid >> 1) * 32;
    const int warpN = (wid & 1) * 64;
    const int bm = blockIdx.y * 128;
    const int bn = blockIdx.x * 128;

    // loader coordinates
    const int row = tid >> 1;            // 0..127  (A row; BMODE0 B row)
    const int kc  = (tid & 1) * 16;      // float col 0 or 16
    const int krow = tid >> 3;           // 0..31   (BMODE1 B k-row)
    const int ncB  = (tid & 7) * 16;     // BMODE1 B n-col base

    float acc[2][8][4];
    #pragma unroll
    for (int i = 0; i < 2; i++)
        #pragma unroll
        for (int j = 0; j < 8; j++)
            #pragma unroll
            for (int q = 0; q < 4; q++) acc[i][j][q] = 0.f;

    float4 ra[4], rb[4];
    const float4 z4 = make_float4(0.f, 0.f, 0.f, 0.f);

    auto ldg_stage = [&](int k0) {
        const float* ap = A + (size_t)(bm + row) * lda + k0 + kc;
        #pragma unroll
        for (int c = 0; c < 4; c++)
            ra[c] = (k0 + kc + c * 4 + 4 <= K) ? *(const float4*)(ap + c * 4) : z4;
        if (BMODE == 0) {
            const float* bp = B + (size_t)(bn + row) * ldb + k0 + kc;
            #pragma unroll
            for (int c = 0; c < 4; c++)
                rb[c] = (k0 + kc + c * 4 + 4 <= K) ? *(const float4*)(bp + c * 4) : z4;
        } else {
            const float* bp = B + (size_t)(k0 + krow) * ldb + bn + ncB;
            #pragma unroll
            for (int c = 0; c < 4; c++)
                rb[c] = (bn + ncB + c * 4 + 4 <= N) ? *(const float4*)(bp + c * 4) : z4;
        }
    };

    auto sts_stage = [&](int buf) {
        #pragma unroll
        for (int c = 0; c < 4; c++) {
            int chunk = (kc >> 2) + c;
            *(float4*)&As[buf][row][(chunk ^ (row & 7)) << 2] = cvt4(ra[c]);
        }
        if (BMODE == 0) {
            #pragma unroll
            for (int c = 0; c < 4; c++) {
                int chunk = (kc >> 2) + c;
                *(float4*)&Bs0[buf][row][(chunk ^ (row & 7)) << 2] = cvt4(rb[c]);
            }
        } else {
            #pragma unroll
            for (int c = 0; c < 4; c++)
                *(float4*)&Bs1[buf][krow][ncB + c * 4] = cvt4(rb[c]);
        }
    };

    auto compute_stage = [&](int buf) {
        #pragma unroll
        for (int ko = 0; ko < 4; ko++) {     // koff = ko*8
            const int cc0 = (((ko * 2)     ^ g4) << 2) | kl;  // cols koff..koff+3
            const int cc1 = (((ko * 2 + 1) ^ g4) << 2) | kl;  // cols koff+4..+7
            uint32_t af[2][4], bf[8][2];
            #pragma unroll
            for (int mt = 0; mt < 2; mt++) {
                int m = warpM + mt * 16 + g4;
                af[mt][0] = __float_as_uint(As[buf][m][cc0]);
                af[mt][1] = __float_as_uint(As[buf][m + 8][cc0]);
                af[mt][2] = __float_as_uint(As[buf][m][cc1]);
                af[mt][3] = __float_as_uint(As[buf][m + 8][cc1]);
            }
            if (BMODE == 0) {
                #pragma unroll
                for (int nt = 0; nt < 8; nt++) {
                    int n = warpN + nt * 8 + g4;
                    bf[nt][0] = __float_as_uint(Bs0[buf][n][cc0]);
                    bf[nt][1] = __float_as_uint(Bs0[buf][n][cc1]);
                }
            } else {
                #pragma unroll
                for (int nt = 0; nt < 8; nt++) {
                    int n = warpN + nt * 8 + g4;
                    bf[nt][0] = __float_as_uint(Bs1[buf][ko * 8 + kl][n]);
                    bf[nt][1] = __float_as_uint(Bs1[buf][ko * 8 + kl + 4][n]);
                }
            }
            #pragma unroll
            for (int mt = 0; mt < 2; mt++)
                #pragma unroll
                for (int nt = 0; nt < 8; nt++)
                    mma_tf32(acc[mt][nt], af[mt][0], af[mt][1], af[mt][2], af[mt][3],
                             bf[nt][0], bf[nt][1]);
        }
    };

    const int nst = (K + BK - 1) / BK;
    ldg_stage(0);
    sts_stage(0);
    __syncthreads();
    for (int s = 0; s < nst; s++) {
        bool more = (s + 1 < nst);
        if (more) ldg_stage((s + 1) * BK);   // LDG overlaps compute below
        compute_stage(s & 1);
        if (more) sts_stage((s + 1) & 1);    // writes other buffer — safe
        __syncthreads();
    }

    // ---- epilogue ----
    #pragma unroll
    for (int mt = 0; mt < 2; mt++) {
        #pragma unroll
        for (int rr = 0; rr < 2; rr++) {
            int r_ = bm + warpM + mt * 16 + g4 + rr * 8;
            float* Crow = C + (size_t)r_ * ldc;
            const float* Rrow = Rsd ? (Rsd + (size_t)r_ * ldr) : nullptr;
            #pragma unroll
            for (int nt = 0; nt < 8; nt++) {
                int col = bn + warpN + nt * 8 + kl * 2;
                if (col < N) {
                    float v0 = acc[mt][nt][rr * 2 + 0] * alpha;
                    float v1 = acc[mt][nt][rr * 2 + 1] * alpha;
                    if (bias) { v0 += bias[col]; v1 += bias[col + 1]; }
                    if (ACT == 1) { v0 = gelu_tanh(v0); v1 = gelu_tanh(v1); }
                    if (Rrow) { v0 += Rrow[col]; v1 += Rrow[col + 1]; }
                    *(float2*)(Crow + col) = make_float2(v0, v1);
                }
            }
        }
    }
}

// ---------------- launch ----------------------------------------------------
extern "C" void kernel_launch(void* const* d_in, const int* in_sizes, int n_in,
                              void* d_out, int out_size) {
    const float* x      = (const float*)d_in[0];
    const float* mask   = (const float*)d_in[1];
    const float* cosp   = (const float*)d_in[2];
    const float* sinp   = (const float*)d_in[3];
    const float* qkv_w  = (const float*)d_in[4];
    const float* qkv_b  = (const float*)d_in[5];
    const float* proj_w = (const float*)d_in[6];
    const float* proj_b = (const float*)d_in[7];
    const float* fc1_w  = (const float*)d_in[8];
    const float* fc1_b  = (const float*)d_in[9];
    const float* fc2_w  = (const float*)d_in[10];
    const float* fc2_b  = (const float*)d_in[11];
    const float* ln1_g  = (const float*)d_in[12];
    const float* ln1_b  = (const float*)d_in[13];
    const float* ln2_g  = (const float*)d_in[14];
    const float* ln2_b  = (const float*)d_in[15];
    float* out = (float*)d_out;

    float *p_ln, *p_qkv, *p_attn, *p_ctx, *p_x1, *p_ffn;
    cudaGetSymbolAddress((void**)&p_ln,   g_ln);
    cudaGetSymbolAddress((void**)&p_qkv,  g_qkv);
    cudaGetSymbolAddress((void**)&p_attn, g_attn);
    cudaGetSymbolAddress((void**)&p_ctx,  g_ctx);
    cudaGetSymbolAddress((void**)&p_x1,   g_x1);
    cudaGetSymbolAddress((void**)&p_ffn,  g_ffn);

    const int SM0 = 32768 + 2 * 128 * 32 * 4;   // 65536
    const int SM1 = 32768 + 2 * 32 * 136 * 4;   // 67584
    cudaFuncSetAttribute(mma_gemm<0, 0>, cudaFuncAttributeMaxDynamicSharedMemorySize, SM0);
    cudaFuncSetAttribute(mma_gemm<0, 1>, cudaFuncAttributeMaxDynamicSharedMemorySize, SM0);
    cudaFuncSetAttribute(mma_gemm<1, 0>, cudaFuncAttributeMaxDynamicSharedMemorySize, SM1);

    // 1. LN1
    ln_kernel<<<SS, 256>>>(x, ln1_g, ln1_b, p_ln);

    // 2. QKV = ln @ qkv_w^T + qkv_b   (4096 x 3840 x 1280)
    mma_gemm<0, 0><<<dim3(3840 / 128, SS / 128), 256, SM0>>>(
        p_ln, HH, 0, qkv_w, HH, 0, p_qkv, 3 * HH, 0,
        qkv_b, nullptr, 0, 3 * HH, HH, 1.f);

    // 3. RoPE on q, k in place
    {
        int n = SS * NHEAD * (HDIM / 2);
        rope_kernel<<<(n + 255) / 256, 256>>>(p_qkv, cosp, sinp);
    }

    // 4. scores[h] = Q_h @ K_h^T * scaling   (batched over 16 heads)
    mma_gemm<0, 0><<<dim3(SS / 128, SS / 128, NHEAD), 256, SM0>>>(
        p_qkv, 3 * HH, HDIM,
        p_qkv + HH, 3 * HH, HDIM,
        p_attn, SS, (long long)SS * SS,
        nullptr, nullptr, 0, SS, HDIM, rsqrtf((float)HDIM));

    // 5. softmax(+mask)
    softmax_kernel<<<dim3(SS, NHEAD), 256>>>(p_attn, mask);

    // 6. ctx[h] = attn_h @ V_h   (M=4096, N=80, K=4096)
    mma_gemm<1, 0><<<dim3(1, SS / 128, NHEAD), 256, SM1>>>(
        p_attn, SS, (long long)SS * SS,
        p_qkv + 2 * HH, 3 * HH, HDIM,
        p_ctx, HH, HDIM,
        nullptr, nullptr, 0, HDIM, SS, 1.f);

    // 7. x1 = x + ctx @ proj_w^T + proj_b
    mma_gemm<0, 0><<<dim3(HH / 128, SS / 128), 256, SM0>>>(
        p_ctx, HH, 0, proj_w, HH, 0, p_x1, HH, 0,
        proj_b, x, HH, HH, HH, 1.f);

    // 8. LN2
    ln_kernel<<<SS, 256>>>(p_x1, ln2_g, ln2_b, p_ln);

    // 9. ffn = gelu(ln @ fc1_w^T + fc1_b)
    mma_gemm<0, 1><<<dim3(IDIM / 128, SS / 128), 256, SM0>>>(
        p_ln, HH, 0, fc1_w, HH, 0, p_ffn, IDIM, 0,
        fc1_b, nullptr, 0, IDIM, HH, 1.f);

    // 10. out = x1 + ffn @ fc2_w^T + fc2_b
    mma_gemm<0, 0><<<dim3(HH / 128, SS / 128), 256, SM0>>>(
        p_ffn, IDIM, 0, fc2_w, IDIM, 0, out, HH, 0,
        fc2_b, p_x1, HH, HH, IDIM, 1.f);
}

// round 7
// speedup vs baseline: 2.6251x; 1.0990x over previous
#include <cuda_runtime.h>
#include <math.h>
#include <stdint.h>

#define SS 4096
#define HH 1280
#define NHEAD 16
#define HDIM 80
#define IDIM 5120
#define EPSV 1e-6f

// ---------------- scratch (static device memory; no allocs allowed) --------
__device__ float g_ln  [(size_t)SS * HH];
__device__ float g_qkv [(size_t)SS * 3 * HH];
__device__ float g_ctx [(size_t)SS * HH];
__device__ float g_x1  [(size_t)SS * HH];
__device__ float g_ffn [(size_t)SS * IDIM];

// ---------------- helpers ---------------------------------------------------
__device__ __forceinline__ float to_tf32(float x) {
    float r;
    asm("cvt.rna.tf32.f32 %0, %1;" : "=f"(r) : "f"(x));
    return r;
}
__device__ __forceinline__ float4 cvt4(float4 v) {
    v.x = to_tf32(v.x); v.y = to_tf32(v.y); v.z = to_tf32(v.z); v.w = to_tf32(v.w);
    return v;
}
__device__ __forceinline__ void mma_tf32(float* d, uint32_t a0, uint32_t a1,
                                         uint32_t a2, uint32_t a3,
                                         uint32_t b0, uint32_t b1) {
    asm volatile(
        "mma.sync.aligned.m16n8k8.row.col.f32.tf32.tf32.f32 "
        "{%0,%1,%2,%3}, {%4,%5,%6,%7}, {%8,%9}, {%0,%1,%2,%3};"
        : "+f"(d[0]), "+f"(d[1]), "+f"(d[2]), "+f"(d[3])
        : "r"(a0), "r"(a1), "r"(a2), "r"(a3), "r"(b0), "r"(b1));
}

// ---------------- reductions ----------------------------------------------
__device__ __forceinline__ float block_reduce_sum(float v) {
    __shared__ float sh_sum[32];
    int lane = threadIdx.x & 31, wid = threadIdx.x >> 5;
    #pragma unroll
    for (int o = 16; o; o >>= 1) v += __shfl_xor_sync(0xffffffffu, v, o);
    if (lane == 0) sh_sum[wid] = v;
    __syncthreads();
    v = (threadIdx.x < (blockDim.x >> 5)) ? sh_sum[threadIdx.x] : 0.f;
    if (wid == 0) {
        #pragma unroll
        for (int o = 16; o; o >>= 1) v += __shfl_xor_sync(0xffffffffu, v, o);
        if (lane == 0) sh_sum[0] = v;
    }
    __syncthreads();
    float r = sh_sum[0];
    __syncthreads();
    return r;
}

// ---------------- layernorm -------------------------------------------------
__global__ void ln_kernel(const float* __restrict__ x, const float* __restrict__ g,
                          const float* __restrict__ b, float* __restrict__ out) {
    int row = blockIdx.x;
    const float* xr = x + (size_t)row * HH;
    float v[5]; float s = 0.f;
    #pragma unroll
    for (int i = 0; i < 5; i++) { v[i] = xr[threadIdx.x + i * 256]; s += v[i]; }
    float mean = block_reduce_sum(s) * (1.f / HH);
    float vs = 0.f;
    #pragma unroll
    for (int i = 0; i < 5; i++) { float d = v[i] - mean; vs += d * d; }
    float var = block_reduce_sum(vs) * (1.f / HH);
    float inv = rsqrtf(var + EPSV);
    float* o = out + (size_t)row * HH;
    #pragma unroll
    for (int i = 0; i < 5; i++) {
        int c = threadIdx.x + i * 256;
        o[c] = (v[i] - mean) * inv * g[c] + b[c];
    }
}

// ---------------- RoPE ------------------------------------------------------
__global__ void rope_kernel(float* __restrict__ qkv, const float* __restrict__ cs,
                            const float* __restrict__ sn) {
    int idx = blockIdx.x * blockDim.x + threadIdx.x;
    if (idx >= SS * NHEAD * (HDIM / 2)) return;
    int d = idx % (HDIM / 2);
    int h = (idx / (HDIM / 2)) % NHEAD;
    int s = idx / ((HDIM / 2) * NHEAD);
    float c1 = cs[s * HDIM + d], c2 = cs[s * HDIM + d + 40];
    float s1 = sn[s * HDIM + d], s2 = sn[s * HDIM + d + 40];
    size_t base = (size_t)s * 3 * HH + h * HDIM;
    float* qp = qkv + base;
    float a = qp[d], bb = qp[d + 40];
    qp[d]      = a * c1 - bb * s1;
    qp[d + 40] = bb * c2 + a * s2;
    float* kp = qkv + base + HH;
    a = kp[d]; bb = kp[d + 40];
    kp[d]      = a * c1 - bb * s1;
    kp[d + 40] = bb * c2 + a * s2;
}

__device__ __forceinline__ float gelu_tanh(float x) {
    return 0.5f * x * (1.f + tanhf(0.7978845608028654f * (x + 0.044715f * x * x * x)));
}

// ================= flash attention (tf32 mma) ===============================
// grid (SS/128, NHEAD), 256 threads. Each warp owns 16 Q rows (full KV width).
// Q fragments register-resident. Per 128-row KV tile: S=QK^T (mma), scale+mask,
// online softmax (warp-local), P acc -> A-frags via lane shuffles, O += P*V.
// SMEM: Ks[128][84] (pad 84: frag banks (g4*20+kl)%32 all distinct),
//       VsT[80][132] (transposed; frag bank = lane id, conflict-free).
#define KSPAD 84
#define VSPAD 132
__global__ void __launch_bounds__(256)
flash_kernel(const float* __restrict__ qkv, const float* __restrict__ mask,
             float* __restrict__ ctx) {
    extern __shared__ float fsm[];
    float* Ks  = fsm;                       // 128 * 84
    float* VsT = fsm + 128 * KSPAD;         // 80 * 132

    const int tid  = threadIdx.x;
    const int wid  = tid >> 5;
    const int lane = tid & 31;
    const int g4   = lane >> 2;
    const int kl   = lane & 3;
    const int bm   = blockIdx.x * 128;
    const int h    = blockIdx.y;
    const float scale = rsqrtf((float)HDIM);

    const float* Qb = qkv + h * HDIM;
    const float* Kb = qkv + HH + h * HDIM;
    const float* Vb = qkv + 2 * HH + h * HDIM;

    const int lr = tid >> 1;                // loader row 0..127
    const int lc = (tid & 1) * 40;          // loader col base

    // ---- stage Q tile into Ks, then load Q fragments ----
    {
        const float* src = Qb + (size_t)(bm + lr) * (3 * HH) + lc;
        float* dst = Ks + lr * KSPAD + lc;
        #pragma unroll
        for (int i = 0; i < 10; i++)
            *(float4*)(dst + i * 4) = cvt4(*(const float4*)(src + i * 4));
    }
    __syncthreads();
    uint32_t qa[10][4];
    {
        int r0 = wid * 16 + g4;
        #pragma unroll
        for (int ks = 0; ks < 10; ks++) {
            qa[ks][0] = __float_as_uint(Ks[r0 * KSPAD + ks * 8 + kl]);
            qa[ks][1] = __float_as_uint(Ks[(r0 + 8) * KSPAD + ks * 8 + kl]);
            qa[ks][2] = __float_as_uint(Ks[r0 * KSPAD + ks * 8 + kl + 4]);
            qa[ks][3] = __float_as_uint(Ks[(r0 + 8) * KSPAD + ks * 8 + kl + 4]);
        }
    }

    float Oa[10][4];
    #pragma unroll
    for (int i = 0; i < 10; i++)
        #pragma unroll
        for (int j = 0; j < 4; j++) Oa[i][j] = 0.f;
    float m0 = -INFINITY, m1 = -INFINITY, l0 = 0.f, l1 = 0.f;

    const float* mrow0 = mask + (size_t)(bm + wid * 16 + g4) * SS;
    const float* mrow1 = mrow0 + (size_t)8 * SS;

    const int src_lo = (lane & ~3) | (kl >> 1);
    const int src_hi = src_lo + 2;

    for (int kv0 = 0; kv0 < SS; kv0 += 128) {
        __syncthreads();   // protect smem from previous iteration's readers
        // ---- load K tile (row-major, pad 84) and V tile (transposed) ----
        {
            const float* ksrc = Kb + (size_t)(kv0 + lr) * (3 * HH) + lc;
            float* kd = Ks + lr * KSPAD + lc;
            #pragma unroll
            for (int i = 0; i < 10; i++)
                *(float4*)(kd + i * 4) = cvt4(*(const float4*)(ksrc + i * 4));
            const float* vsrc = Vb + (size_t)(kv0 + lr) * (3 * HH) + lc;
            #pragma unroll
            for (int i = 0; i < 10; i++) {
                float4 v = cvt4(*(const float4*)(vsrc + i * 4));
                int c = lc + i * 4;
                VsT[(c + 0) * VSPAD + lr] = v.x;
                VsT[(c + 1) * VSPAD + lr] = v.y;
                VsT[(c + 2) * VSPAD + lr] = v.z;
                VsT[(c + 3) * VSPAD + lr] = v.w;
            }
        }
        __syncthreads();

        // ---- S = Q K^T (16 n-tiles x 10 k-steps) ----
        float sa[16][4];
        #pragma unroll
        for (int nt = 0; nt < 16; nt++)
            #pragma unroll
            for (int j = 0; j < 4; j++) sa[nt][j] = 0.f;
        #pragma unroll
        for (int ks = 0; ks < 10; ks++) {
            #pragma unroll
            for (int nt = 0; nt < 16; nt++) {
                uint32_t b0 = __float_as_uint(Ks[(nt * 8 + g4) * KSPAD + ks * 8 + kl]);
                uint32_t b1 = __float_as_uint(Ks[(nt * 8 + g4) * KSPAD + ks * 8 + kl + 4]);
                mma_tf32(sa[nt], qa[ks][0], qa[ks][1], qa[ks][2], qa[ks][3], b0, b1);
            }
        }

        // ---- scale + mask + row max ----
        float tmx0 = -INFINITY, tmx1 = -INFINITY;
        #pragma unroll
        for (int nt = 0; nt < 16; nt++) {
            float2 mk0 = *(const float2*)(mrow0 + kv0 + nt * 8 + 2 * kl);
            float2 mk1 = *(const float2*)(mrow1 + kv0 + nt * 8 + 2 * kl);
            sa[nt][0] = sa[nt][0] * scale + mk0.x;
            sa[nt][1] = sa[nt][1] * scale + mk0.y;
            sa[nt][2] = sa[nt][2] * scale + mk1.x;
            sa[nt][3] = sa[nt][3] * scale + mk1.y;
            tmx0 = fmaxf(tmx0, fmaxf(sa[nt][0], sa[nt][1]));
            tmx1 = fmaxf(tmx1, fmaxf(sa[nt][2], sa[nt][3]));
        }
        tmx0 = fmaxf(tmx0, __shfl_xor_sync(0xffffffffu, tmx0, 1));
        tmx0 = fmaxf(tmx0, __shfl_xor_sync(0xffffffffu, tmx0, 2));
        tmx1 = fmaxf(tmx1, __shfl_xor_sync(0xffffffffu, tmx1, 1));
        tmx1 = fmaxf(tmx1, __shfl_xor_sync(0xffffffffu, tmx1, 2));

        float nm0 = fmaxf(m0, tmx0), nm1 = fmaxf(m1, tmx1);
        float f0 = __expf(m0 - nm0), f1 = __expf(m1 - nm1);
        m0 = nm0; m1 = nm1;

        // ---- exp + row sum ----
        float ts0 = 0.f, ts1 = 0.f;
        #pragma unroll
        for (int nt = 0; nt < 16; nt++) {
            sa[nt][0] = __expf(sa[nt][0] - nm0);
            sa[nt][1] = __expf(sa[nt][1] - nm0);
            sa[nt][2] = __expf(sa[nt][2] - nm1);
            sa[nt][3] = __expf(sa[nt][3] - nm1);
            ts0 += sa[nt][0] + sa[nt][1];
            ts1 += sa[nt][2] + sa[nt][3];
        }
        ts0 += __shfl_xor_sync(0xffffffffu, ts0, 1);
        ts0 += __shfl_xor_sync(0xffffffffu, ts0, 2);
        ts1 += __shfl_xor_sync(0xffffffffu, ts1, 1);
        ts1 += __shfl_xor_sync(0xffffffffu, ts1, 2);
        l0 = l0 * f0 + ts0;
        l1 = l1 * f1 + ts1;

        // ---- rescale O ----
        #pragma unroll
        for (int no = 0; no < 10; no++) {
            Oa[no][0] *= f0; Oa[no][1] *= f0;
            Oa[no][2] *= f1; Oa[no][3] *= f1;
        }

        // ---- P (acc layout) -> A-frags via shuffles, then O += P * V ----
        #pragma unroll
        for (int nt = 0; nt < 16; nt++) {
            float p0 = to_tf32(sa[nt][0]), p1 = to_tf32(sa[nt][1]);
            float p2 = to_tf32(sa[nt][2]), p3 = to_tf32(sa[nt][3]);
            float a0l = __shfl_sync(0xffffffffu, p0, src_lo);
            float a0h = __shfl_sync(0xffffffffu, p1, src_lo);
            float a1l = __shfl_sync(0xffffffffu, p2, src_lo);
            float a1h = __shfl_sync(0xffffffffu, p3, src_lo);
            float a2l = __shfl_sync(0xffffffffu, p0, src_hi);
            float a2h = __shfl_sync(0xffffffffu, p1, src_hi);
            float a3l = __shfl_sync(0xffffffffu, p2, src_hi);
            float a3h = __shfl_sync(0xffffffffu, p3, src_hi);
            bool odd = (kl & 1);
            uint32_t A0 = __float_as_uint(odd ? a0h : a0l);
            uint32_t A1 = __float_as_uint(odd ? a1h : a1l);
            uint32_t A2 = __float_as_uint(odd ? a2h : a2l);
            uint32_t A3 = __float_as_uint(odd ? a3h : a3l);
            #pragma unroll
            for (int no = 0; no < 10; no++) {
                uint32_t b0 = __float_as_uint(VsT[(no * 8 + g4) * VSPAD + nt * 8 + kl]);
                uint32_t b1 = __float_as_uint(VsT[(no * 8 + g4) * VSPAD + nt * 8 + kl + 4]);
                mma_tf32(Oa[no], A0, A1, A2, A3, b0, b1);
            }
        }
    }

    // ---- epilogue: O / l -> ctx ----
    float i0 = 1.f / l0, i1 = 1.f / l1;
    int r0 = bm + wid * 16 + g4;
    float* c0p = ctx + (size_t)r0 * HH + h * HDIM;
    float* c1p = c0p + (size_t)8 * HH;
    #pragma unroll
    for (int no = 0; no < 10; no++) {
        *(float2*)(c0p + no * 8 + 2 * kl) = make_float2(Oa[no][0] * i0, Oa[no][1] * i0);
        *(float2*)(c1p + no * 8 + 2 * kl) = make_float2(Oa[no][2] * i1, Oa[no][3] * i1);
    }
}

// ================= TF32 mma.sync GEMM (dense projections) ===================
template<int ACT>
__global__ void __launch_bounds__(256)
mma_gemm(const float* __restrict__ A, int lda,
         const float* __restrict__ B, int ldb,
         float* __restrict__ C, int ldc,
         const float* __restrict__ bias,
         const float* __restrict__ Rsd, int ldr,
         int N, int K, float alpha) {
    constexpr int BK = 32;

    extern __shared__ char smem_raw[];
    float (*As)[128][32] = (float (*)[128][32])(smem_raw);
    float (*Bs0)[128][32] = (float (*)[128][32])(smem_raw + 32768);

    const int tid = threadIdx.x;
    const int wid = tid >> 5;
    const int lane = tid & 31;
    const int kl = lane & 3;
    const int g4 = lane >> 2;
    const int warpM = (wid >> 1) * 32;
    const int warpN = (wid & 1) * 64;
    const int bm = blockIdx.y * 128;
    const int bn = blockIdx.x * 128;

    const int row = tid >> 1;
    const int kc  = (tid & 1) * 16;

    float acc[2][8][4];
    #pragma unroll
    for (int i = 0; i < 2; i++)
        #pragma unroll
        for (int j = 0; j < 8; j++)
            #pragma unroll
            for (int q = 0; q < 4; q++) acc[i][j][q] = 0.f;

    float4 ra[4], rb[4];
    const float4 z4 = make_float4(0.f, 0.f, 0.f, 0.f);

    auto ldg_stage = [&](int k0) {
        const float* ap = A + (size_t)(bm + row) * lda + k0 + kc;
        #pragma unroll
        for (int c = 0; c < 4; c++)
            ra[c] = (k0 + kc + c * 4 + 4 <= K) ? *(const float4*)(ap + c * 4) : z4;
        const float* bp = B + (size_t)(bn + row) * ldb + k0 + kc;
        #pragma unroll
        for (int c = 0; c < 4; c++)
            rb[c] = (k0 + kc + c * 4 + 4 <= K) ? *(const float4*)(bp + c * 4) : z4;
    };

    auto sts_stage = [&](int buf) {
        #pragma unroll
        for (int c = 0; c < 4; c++) {
            int chunk = (kc >> 2) + c;
            *(float4*)&As[buf][row][(chunk ^ (row & 7)) << 2] = cvt4(ra[c]);
            *(float4*)&Bs0[buf][row][(chunk ^ (row & 7)) << 2] = cvt4(rb[c]);
        }
    };

    auto compute_stage = [&](int buf) {
        #pragma unroll
        for (int ko = 0; ko < 4; ko++) {
            const int cc0 = (((ko * 2)     ^ g4) << 2) | kl;
            const int cc1 = (((ko * 2 + 1) ^ g4) << 2) | kl;
            uint32_t af[2][4], bf[8][2];
            #pragma unroll
            for (int mt = 0; mt < 2; mt++) {
                int m = warpM + mt * 16 + g4;
                af[mt][0] = __float_as_uint(As[buf][m][cc0]);
                af[mt][1] = __float_as_uint(As[buf][m + 8][cc0]);
                af[mt][2] = __float_as_uint(As[buf][m][cc1]);
                af[mt][3] = __float_as_uint(As[buf][m + 8][cc1]);
            }
            #pragma unroll
            for (int nt = 0; nt < 8; nt++) {
                int n = warpN + nt * 8 + g4;
                bf[nt][0] = __float_as_uint(Bs0[buf][n][cc0]);
                bf[nt][1] = __float_as_uint(Bs0[buf][n][cc1]);
            }
            #pragma unroll
            for (int mt = 0; mt < 2; mt++)
                #pragma unroll
                for (int nt = 0; nt < 8; nt++)
                    mma_tf32(acc[mt][nt], af[mt][0], af[mt][1], af[mt][2], af[mt][3],
                             bf[nt][0], bf[nt][1]);
        }
    };

    const int nst = (K + BK - 1) / BK;
    ldg_stage(0);
    sts_stage(0);
    __syncthreads();
    for (int s = 0; s < nst; s++) {
        bool more = (s + 1 < nst);
        if (more) ldg_stage((s + 1) * BK);
        compute_stage(s & 1);
        if (more) sts_stage((s + 1) & 1);
        __syncthreads();
    }

    #pragma unroll
    for (int mt = 0; mt < 2; mt++) {
        #pragma unroll
        for (int rr = 0; rr < 2; rr++) {
            int r_ = bm + warpM + mt * 16 + g4 + rr * 8;
            float* Crow = C + (size_t)r_ * ldc;
            const float* Rrow = Rsd ? (Rsd + (size_t)r_ * ldr) : nullptr;
            #pragma unroll
            for (int nt = 0; nt < 8; nt++) {
                int col = bn + warpN + nt * 8 + kl * 2;
                if (col < N) {
                    float v0 = acc[mt][nt][rr * 2 + 0] * alpha;
                    float v1 = acc[mt][nt][rr * 2 + 1] * alpha;
                    if (bias) { v0 += bias[col]; v1 += bias[col + 1]; }
                    if (ACT == 1) { v0 = gelu_tanh(v0); v1 = gelu_tanh(v1); }
                    if (Rrow) { v0 += Rrow[col]; v1 += Rrow[col + 1]; }
                    *(float2*)(Crow + col) = make_float2(v0, v1);
                }
            }
        }
    }
}

// ---------------- launch ----------------------------------------------------
extern "C" void kernel_launch(void* const* d_in, const int* in_sizes, int n_in,
                              void* d_out, int out_size) {
    const float* x      = (const float*)d_in[0];
    const float* mask   = (const float*)d_in[1];
    const float* cosp   = (const float*)d_in[2];
    const float* sinp   = (const float*)d_in[3];
    const float* qkv_w  = (const float*)d_in[4];
    const float* qkv_b  = (const float*)d_in[5];
    const float* proj_w = (const float*)d_in[6];
    const float* proj_b = (const float*)d_in[7];
    const float* fc1_w  = (const float*)d_in[8];
    const float* fc1_b  = (const float*)d_in[9];
    const float* fc2_w  = (const float*)d_in[10];
    const float* fc2_b  = (const float*)d_in[11];
    const float* ln1_g  = (const float*)d_in[12];
    const float* ln1_b  = (const float*)d_in[13];
    const float* ln2_g  = (const float*)d_in[14];
    const float* ln2_b  = (const float*)d_in[15];
    float* out = (float*)d_out;

    float *p_ln, *p_qkv, *p_ctx, *p_x1, *p_ffn;
    cudaGetSymbolAddress((void**)&p_ln,   g_ln);
    cudaGetSymbolAddress((void**)&p_qkv,  g_qkv);
    cudaGetSymbolAddress((void**)&p_ctx,  g_ctx);
    cudaGetSymbolAddress((void**)&p_x1,   g_x1);
    cudaGetSymbolAddress((void**)&p_ffn,  g_ffn);

    const int SMG = 32768 + 2 * 128 * 32 * 4;                 // 65536
    const int SMF = (128 * KSPAD + 80 * VSPAD) * 4;           // 85248
    cudaFuncSetAttribute(mma_gemm<0>, cudaFuncAttributeMaxDynamicSharedMemorySize, SMG);
    cudaFuncSetAttribute(mma_gemm<1>, cudaFuncAttributeMaxDynamicSharedMemorySize, SMG);
    cudaFuncSetAttribute(flash_kernel, cudaFuncAttributeMaxDynamicSharedMemorySize, SMF);

    // 1. LN1
    ln_kernel<<<SS, 256>>>(x, ln1_g, ln1_b, p_ln);

    // 2. QKV = ln @ qkv_w^T + qkv_b   (4096 x 3840 x 1280)
    mma_gemm<0><<<dim3(3840 / 128, SS / 128), 256, SMG>>>(
        p_ln, HH, qkv_w, HH, p_qkv, 3 * HH,
        qkv_b, nullptr, 0, 3 * HH, HH, 1.f);

    // 3. RoPE on q, k in place
    {
        int n = SS * NHEAD * (HDIM / 2);
        rope_kernel<<<(n + 255) / 256, 256>>>(p_qkv, cosp, sinp);
    }

    // 4-6. fused flash attention -> ctx
    flash_kernel<<<dim3(SS / 128, NHEAD), 256, SMF>>>(p_qkv, mask, p_ctx);

    // 7. x1 = x + ctx @ proj_w^T + proj_b
    mma_gemm<0><<<dim3(HH / 128, SS / 128), 256, SMG>>>(
        p_ctx, HH, proj_w, HH, p_x1, HH,
        proj_b, x, HH, HH, HH, 1.f);

    // 8. LN2
    ln_kernel<<<SS, 256>>>(p_x1, ln2_g, ln2_b, p_ln);

    // 9. ffn = gelu(ln @ fc1_w^T + fc1_b)
    mma_gemm<1><<<dim3(IDIM / 128, SS / 128), 256, SMG>>>(
        p_ln, HH, fc1_w, HH, p_ffn, IDIM,
        fc1_b, nullptr, 0, IDIM, HH, 1.f);

    // 10. out = x1 + ffn @ fc2_w^T + fc2_b
    mma_gemm<0><<<dim3(HH / 128, SS / 128), 256, SMG>>>(
        p_ffn, IDIM, fc2_w, IDIM, out, HH,
        fc2_b, p_x1, HH, HH, IDIM, 1.f);
}

// round 8
// speedup vs baseline: 3.6050x; 1.3733x over previous
#include <cuda_runtime.h>
#include <math.h>
#include <stdint.h>

#define SS 4096
#define HH 1280
#define NHEAD 16
#define HDIM 80
#define IDIM 5120
#define EPSV 1e-6f

// ---------------- scratch (static device memory; no allocs allowed) --------
__device__ float g_ln  [(size_t)SS * HH];
__device__ float g_qkv [(size_t)SS * 3 * HH];
__device__ float g_ctx [(size_t)SS * HH];
__device__ float g_x1  [(size_t)SS * HH];
__device__ float g_ffn [(size_t)SS * IDIM];

// ---------------- helpers ---------------------------------------------------
__device__ __forceinline__ float to_tf32(float x) {
    float r;
    asm("cvt.rna.tf32.f32 %0, %1;" : "=f"(r) : "f"(x));
    return r;
}
__device__ __forceinline__ float4 cvt4(float4 v) {
    v.x = to_tf32(v.x); v.y = to_tf32(v.y); v.z = to_tf32(v.z); v.w = to_tf32(v.w);
    return v;
}
__device__ __forceinline__ uint32_t smem_u32(const void* p) {
    uint32_t a;
    asm("{ .reg .u64 t; cvta.to.shared.u64 t, %1; cvt.u32.u64 %0, t; }" : "=r"(a) : "l"(p));
    return a;
}
__device__ __forceinline__ void mma_tf32(float* d, uint32_t a0, uint32_t a1,
                                         uint32_t a2, uint32_t a3,
                                         uint32_t b0, uint32_t b1) {
    asm volatile(
        "mma.sync.aligned.m16n8k8.row.col.f32.tf32.tf32.f32 "
        "{%0,%1,%2,%3}, {%4,%5,%6,%7}, {%8,%9}, {%0,%1,%2,%3};"
        : "+f"(d[0]), "+f"(d[1]), "+f"(d[2]), "+f"(d[3])
        : "r"(a0), "r"(a1), "r"(a2), "r"(a3), "r"(b0), "r"(b1));
}
#define CP_ASYNC16(dst, src) \
    asm volatile("cp.async.cg.shared.global [%0], [%1], 16;" :: "r"(dst), "l"(src) : "memory")
#define CP_COMMIT() asm volatile("cp.async.commit_group;" ::: "memory")
#define CP_WAIT(n)  asm volatile("cp.async.wait_group %0;" :: "n"(n) : "memory")

// ---------------- reductions ----------------------------------------------
__device__ __forceinline__ float block_reduce_sum(float v) {
    __shared__ float sh_sum[32];
    int lane = threadIdx.x & 31, wid = threadIdx.x >> 5;
    #pragma unroll
    for (int o = 16; o; o >>= 1) v += __shfl_xor_sync(0xffffffffu, v, o);
    if (lane == 0) sh_sum[wid] = v;
    __syncthreads();
    v = (threadIdx.x < (blockDim.x >> 5)) ? sh_sum[threadIdx.x] : 0.f;
    if (wid == 0) {
        #pragma unroll
        for (int o = 16; o; o >>= 1) v += __shfl_xor_sync(0xffffffffu, v, o);
        if (lane == 0) sh_sum[0] = v;
    }
    __syncthreads();
    float r = sh_sum[0];
    __syncthreads();
    return r;
}

// ---------------- layernorm -------------------------------------------------
__global__ void ln_kernel(const float* __restrict__ x, const float* __restrict__ g,
                          const float* __restrict__ b, float* __restrict__ out) {
    int row = blockIdx.x;
    const float* xr = x + (size_t)row * HH;
    float v[5]; float s = 0.f;
    #pragma unroll
    for (int i = 0; i < 5; i++) { v[i] = xr[threadIdx.x + i * 256]; s += v[i]; }
    float mean = block_reduce_sum(s) * (1.f / HH);
    float vs = 0.f;
    #pragma unroll
    for (int i = 0; i < 5; i++) { float d = v[i] - mean; vs += d * d; }
    float var = block_reduce_sum(vs) * (1.f / HH);
    float inv = rsqrtf(var + EPSV);
    float* o = out + (size_t)row * HH;
    #pragma unroll
    for (int i = 0; i < 5; i++) {
        int c = threadIdx.x + i * 256;
        o[c] = (v[i] - mean) * inv * g[c] + b[c];
    }
}

// ---------------- RoPE ------------------------------------------------------
__global__ void rope_kernel(float* __restrict__ qkv, const float* __restrict__ cs,
                            const float* __restrict__ sn) {
    int idx = blockIdx.x * blockDim.x + threadIdx.x;
    if (idx >= SS * NHEAD * (HDIM / 2)) return;
    int d = idx % (HDIM / 2);
    int h = (idx / (HDIM / 2)) % NHEAD;
    int s = idx / ((HDIM / 2) * NHEAD);
    float c1 = cs[s * HDIM + d], c2 = cs[s * HDIM + d + 40];
    float s1 = sn[s * HDIM + d], s2 = sn[s * HDIM + d + 40];
    size_t base = (size_t)s * 3 * HH + h * HDIM;
    float* qp = qkv + base;
    float a = qp[d], bb = qp[d + 40];
    qp[d]      = a * c1 - bb * s1;
    qp[d + 40] = bb * c2 + a * s2;
    float* kp = qkv + base + HH;
    a = kp[d]; bb = kp[d + 40];
    kp[d]      = a * c1 - bb * s1;
    kp[d + 40] = bb * c2 + a * s2;
}

__device__ __forceinline__ float gelu_tanh(float x) {
    return 0.5f * x * (1.f + tanhf(0.7978845608028654f * (x + 0.044715f * x * x * x)));
}

// ================= flash attention (tf32 mma) ===============================
#define KSPAD 84
#define VSPAD 132
__global__ void __launch_bounds__(256)
flash_kernel(const float* __restrict__ qkv, const float* __restrict__ mask,
             float* __restrict__ ctx) {
    extern __shared__ float fsm[];
    float* Ks  = fsm;                       // 128 * 84
    float* VsT = fsm + 128 * KSPAD;         // 80 * 132

    const int tid  = threadIdx.x;
    const int wid  = tid >> 5;
    const int lane = tid & 31;
    const int g4   = lane >> 2;
    const int kl   = lane & 3;
    const int bm   = blockIdx.x * 128;
    const int h    = blockIdx.y;
    const float scale = rsqrtf((float)HDIM);

    const float* Qb = qkv + h * HDIM;
    const float* Kb = qkv + HH + h * HDIM;
    const float* Vb = qkv + 2 * HH + h * HDIM;

    const int lr = tid >> 1;
    const int lc = (tid & 1) * 40;

    {
        const float* src = Qb + (size_t)(bm + lr) * (3 * HH) + lc;
        float* dst = Ks + lr * KSPAD + lc;
        #pragma unroll
        for (int i = 0; i < 10; i++)
            *(float4*)(dst + i * 4) = cvt4(*(const float4*)(src + i * 4));
    }
    __syncthreads();
    uint32_t qa[10][4];
    {
        int r0 = wid * 16 + g4;
        #pragma unroll
        for (int ks = 0; ks < 10; ks++) {
            qa[ks][0] = __float_as_uint(Ks[r0 * KSPAD + ks * 8 + kl]);
            qa[ks][1] = __float_as_uint(Ks[(r0 + 8) * KSPAD + ks * 8 + kl]);
            qa[ks][2] = __float_as_uint(Ks[r0 * KSPAD + ks * 8 + kl + 4]);
            qa[ks][3] = __float_as_uint(Ks[(r0 + 8) * KSPAD + ks * 8 + kl + 4]);
        }
    }

    float Oa[10][4];
    #pragma unroll
    for (int i = 0; i < 10; i++)
        #pragma unroll
        for (int j = 0; j < 4; j++) Oa[i][j] = 0.f;
    float m0 = -INFINITY, m1 = -INFINITY, l0 = 0.f, l1 = 0.f;

    const float* mrow0 = mask + (size_t)(bm + wid * 16 + g4) * SS;
    const float* mrow1 = mrow0 + (size_t)8 * SS;

    const int src_lo = (lane & ~3) | (kl >> 1);
    const int src_hi = src_lo + 2;

    for (int kv0 = 0; kv0 < SS; kv0 += 128) {
        __syncthreads();
        {
            const float* ksrc = Kb + (size_t)(kv0 + lr) * (3 * HH) + lc;
            float* kd = Ks + lr * KSPAD + lc;
            #pragma unroll
            for (int i = 0; i < 10; i++)
                *(float4*)(kd + i * 4) = cvt4(*(const float4*)(ksrc + i * 4));
            const float* vsrc = Vb + (size_t)(kv0 + lr) * (3 * HH) + lc;
            #pragma unroll
            for (int i = 0; i < 10; i++) {
                float4 v = cvt4(*(const float4*)(vsrc + i * 4));
                int c = lc + i * 4;
                VsT[(c + 0) * VSPAD + lr] = v.x;
                VsT[(c + 1) * VSPAD + lr] = v.y;
                VsT[(c + 2) * VSPAD + lr] = v.z;
                VsT[(c + 3) * VSPAD + lr] = v.w;
            }
        }
        __syncthreads();

        float sa[16][4];
        #pragma unroll
        for (int nt = 0; nt < 16; nt++)
            #pragma unroll
            for (int j = 0; j < 4; j++) sa[nt][j] = 0.f;
        #pragma unroll
        for (int ks = 0; ks < 10; ks++) {
            #pragma unroll
            for (int nt = 0; nt < 16; nt++) {
                uint32_t b0 = __float_as_uint(Ks[(nt * 8 + g4) * KSPAD + ks * 8 + kl]);
                uint32_t b1 = __float_as_uint(Ks[(nt * 8 + g4) * KSPAD + ks * 8 + kl + 4]);
                mma_tf32(sa[nt], qa[ks][0], qa[ks][1], qa[ks][2], qa[ks][3], b0, b1);
            }
        }

        float tmx0 = -INFINITY, tmx1 = -INFINITY;
        #pragma unroll
        for (int nt = 0; nt < 16; nt++) {
            float2 mk0 = *(const float2*)(mrow0 + kv0 + nt * 8 + 2 * kl);
            float2 mk1 = *(const float2*)(mrow1 + kv0 + nt * 8 + 2 * kl);
            sa[nt][0] = sa[nt][0] * scale + mk0.x;
            sa[nt][1] = sa[nt][1] * scale + mk0.y;
            sa[nt][2] = sa[nt][2] * scale + mk1.x;
            sa[nt][3] = sa[nt][3] * scale + mk1.y;
            tmx0 = fmaxf(tmx0, fmaxf(sa[nt][0], sa[nt][1]));
            tmx1 = fmaxf(tmx1, fmaxf(sa[nt][2], sa[nt][3]));
        }
        tmx0 = fmaxf(tmx0, __shfl_xor_sync(0xffffffffu, tmx0, 1));
        tmx0 = fmaxf(tmx0, __shfl_xor_sync(0xffffffffu, tmx0, 2));
        tmx1 = fmaxf(tmx1, __shfl_xor_sync(0xffffffffu, tmx1, 1));
        tmx1 = fmaxf(tmx1, __shfl_xor_sync(0xffffffffu, tmx1, 2));

        float nm0 = fmaxf(m0, tmx0), nm1 = fmaxf(m1, tmx1);
        float f0 = __expf(m0 - nm0), f1 = __expf(m1 - nm1);
        m0 = nm0; m1 = nm1;

        float ts0 = 0.f, ts1 = 0.f;
        #pragma unroll
        for (int nt = 0; nt < 16; nt++) {
            sa[nt][0] = __expf(sa[nt][0] - nm0);
            sa[nt][1] = __expf(sa[nt][1] - nm0);
            sa[nt][2] = __expf(sa[nt][2] - nm1);
            sa[nt][3] = __expf(sa[nt][3] - nm1);
            ts0 += sa[nt][0] + sa[nt][1];
            ts1 += sa[nt][2] + sa[nt][3];
        }
        ts0 += __shfl_xor_sync(0xffffffffu, ts0, 1);
        ts0 += __shfl_xor_sync(0xffffffffu, ts0, 2);
        ts1 += __shfl_xor_sync(0xffffffffu, ts1, 1);
        ts1 += __shfl_xor_sync(0xffffffffu, ts1, 2);
        l0 = l0 * f0 + ts0;
        l1 = l1 * f1 + ts1;

        #pragma unroll
        for (int no = 0; no < 10; no++) {
            Oa[no][0] *= f0; Oa[no][1] *= f0;
            Oa[no][2] *= f1; Oa[no][3] *= f1;
        }

        #pragma unroll
        for (int nt = 0; nt < 16; nt++) {
            float p0 = to_tf32(sa[nt][0]), p1 = to_tf32(sa[nt][1]);
            float p2 = to_tf32(sa[nt][2]), p3 = to_tf32(sa[nt][3]);
            float a0l = __shfl_sync(0xffffffffu, p0, src_lo);
            float a0h = __shfl_sync(0xffffffffu, p1, src_lo);
            float a1l = __shfl_sync(0xffffffffu, p2, src_lo);
            float a1h = __shfl_sync(0xffffffffu, p3, src_lo);
            float a2l = __shfl_sync(0xffffffffu, p0, src_hi);
            float a2h = __shfl_sync(0xffffffffu, p1, src_hi);
            float a3l = __shfl_sync(0xffffffffu, p2, src_hi);
            float a3h = __shfl_sync(0xffffffffu, p3, src_hi);
            bool odd = (kl & 1);
            uint32_t A0 = __float_as_uint(odd ? a0h : a0l);
            uint32_t A1 = __float_as_uint(odd ? a1h : a1l);
            uint32_t A2 = __float_as_uint(odd ? a2h : a2l);
            uint32_t A3 = __float_as_uint(odd ? a3h : a3l);
            #pragma unroll
            for (int no = 0; no < 10; no++) {
                uint32_t b0 = __float_as_uint(VsT[(no * 8 + g4) * VSPAD + nt * 8 + kl]);
                uint32_t b1 = __float_as_uint(VsT[(no * 8 + g4) * VSPAD + nt * 8 + kl + 4]);
                mma_tf32(Oa[no], A0, A1, A2, A3, b0, b1);
            }
        }
    }

    float i0 = 1.f / l0, i1 = 1.f / l1;
    int r0 = bm + wid * 16 + g4;
    float* c0p = ctx + (size_t)r0 * HH + h * HDIM;
    float* c1p = c0p + (size_t)8 * HH;
    #pragma unroll
    for (int no = 0; no < 10; no++) {
        *(float2*)(c0p + no * 8 + 2 * kl) = make_float2(Oa[no][0] * i0, Oa[no][1] * i0);
        *(float2*)(c1p + no * 8 + 2 * kl) = make_float2(Oa[no][2] * i1, Oa[no][3] * i1);
    }
}

// ================= TF32 GEMM v3: cp.async 3-stage, 64x64 warp tile ==========
// C[m,n] = sum_k A[m,k] * B[n,k]  (+bias, act, +residual)
// CTA 128x128x32, 128 threads = 4 warps (2m x 2n), warp tile 64x64.
// 3-stage cp.async pipeline; tf32 via HW truncation (mma reads tf32 bits).
// SMEM per stage: As 128x32 + Bs 128x32 floats (32KB); chunk-XOR swizzle.
// Requires M,N % 128 == 0 and K % 32 == 0 (all call sites exact).
template<int ACT>
__global__ void __launch_bounds__(128)
mma_gemm(const float* __restrict__ A, int lda,
         const float* __restrict__ B, int ldb,
         float* __restrict__ C, int ldc,
         const float* __restrict__ bias,
         const float* __restrict__ Rsd, int ldr,
         int N, int K) {
    extern __shared__ float sm[];           // 3 stages x 8192 floats
    const uint32_t smb = smem_u32(sm);

    const int tid = threadIdx.x;
    const int wid = tid >> 5;
    const int lane = tid & 31;
    const int g4 = lane >> 2;
    const int kl = lane & 3;
    const int warpM = (wid >> 1) * 64;
    const int warpN = (wid & 1) * 64;
    const int bm = blockIdx.y * 128;
    const int bn = blockIdx.x * 128;

    float acc[4][8][4];
    #pragma unroll
    for (int i = 0; i < 4; i++)
        #pragma unroll
        for (int j = 0; j < 8; j++)
            #pragma unroll
            for (int q = 0; q < 4; q++) acc[i][j][q] = 0.f;

    // issue one stage: 128x32 A + 128x32 B via cp.async (16B each)
    // chunk linearization: idx = i*128 + tid -> row = idx>>3, col = idx&7
    // consecutive 8 lanes read 8 consecutive 16B chunks (128B coalesced).
    auto issue = [&](int k0, int st) {
        uint32_t ab = smb + st * 32768;
        uint32_t bb = ab + 16384;
        #pragma unroll
        for (int i = 0; i < 8; i++) {
            int idx = i * 128 + tid;
            int row = idx >> 3, col = idx & 7;
            uint32_t sw = (uint32_t)((col ^ (row & 7)) << 4);
            CP_ASYNC16(ab + row * 128 + sw, A + (size_t)(bm + row) * lda + k0 + col * 4);
            CP_ASYNC16(bb + row * 128 + sw, B + (size_t)(bn + row) * ldb + k0 + col * 4);
        }
        CP_COMMIT();
    };

    auto compute = [&](int st) {
        const float* As = sm + st * 8192;
        const float* Bs = As + 4096;
        #pragma unroll
        for (int ko = 0; ko < 4; ko++) {
            const int cc0 = (((ko * 2)     ^ g4) << 2) | kl;
            const int cc1 = (((ko * 2 + 1) ^ g4) << 2) | kl;
            uint32_t af[4][4], bf[8][2];
            #pragma unroll
            for (int mt = 0; mt < 4; mt++) {
                int m = warpM + mt * 16 + g4;
                af[mt][0] = __float_as_uint(As[m * 32 + cc0]);
                af[mt][1] = __float_as_uint(As[(m + 8) * 32 + cc0]);
                af[mt][2] = __float_as_uint(As[m * 32 + cc1]);
                af[mt][3] = __float_as_uint(As[(m + 8) * 32 + cc1]);
            }
            #pragma unroll
            for (int nt = 0; nt < 8; nt++) {
                int n = warpN + nt * 8 + g4;
                bf[nt][0] = __float_as_uint(Bs[n * 32 + cc0]);
                bf[nt][1] = __float_as_uint(Bs[n * 32 + cc1]);
            }
            #pragma unroll
            for (int mt = 0; mt < 4; mt++)
                #pragma unroll
                for (int nt = 0; nt < 8; nt++)
                    mma_tf32(acc[mt][nt], af[mt][0], af[mt][1], af[mt][2], af[mt][3],
                             bf[nt][0], bf[nt][1]);
        }
    };

    const int nst = K / 32;
    issue(0, 0);
    if (nst > 1) issue(32, 1);
    int st = 0;
    for (int s = 0; s < nst; s++) {
        if (s + 1 < nst) { CP_WAIT(1); } else { CP_WAIT(0); }
        __syncthreads();
        if (s + 2 < nst) {
            int st2 = st + 2; if (st2 >= 3) st2 -= 3;
            issue((s + 2) * 32, st2);
        }
        compute(st);
        if (++st == 3) st = 0;
    }

    // ---- epilogue ----
    #pragma unroll
    for (int mt = 0; mt < 4; mt++) {
        #pragma unroll
        for (int rr = 0; rr < 2; rr++) {
            int r_ = bm + warpM + mt * 16 + g4 + rr * 8;
            float* Crow = C + (size_t)r_ * ldc;
            const float* Rrow = Rsd ? (Rsd + (size_t)r_ * ldr) : nullptr;
            #pragma unroll
            for (int nt = 0; nt < 8; nt++) {
                int col = bn + warpN + nt * 8 + kl * 2;
                float v0 = acc[mt][nt][rr * 2 + 0];
                float v1 = acc[mt][nt][rr * 2 + 1];
                if (bias) { v0 += bias[col]; v1 += bias[col + 1]; }
                if (ACT == 1) { v0 = gelu_tanh(v0); v1 = gelu_tanh(v1); }
                if (Rrow) { v0 += Rrow[col]; v1 += Rrow[col + 1]; }
                *(float2*)(Crow + col) = make_float2(v0, v1);
            }
        }
    }
}

// ---------------- launch ----------------------------------------------------
extern "C" void kernel_launch(void* const* d_in, const int* in_sizes, int n_in,
                              void* d_out, int out_size) {
    const float* x      = (const float*)d_in[0];
    const float* mask   = (const float*)d_in[1];
    const float* cosp   = (const float*)d_in[2];
    const float* sinp   = (const float*)d_in[3];
    const float* qkv_w  = (const float*)d_in[4];
    const float* qkv_b  = (const float*)d_in[5];
    const float* proj_w = (const float*)d_in[6];
    const float* proj_b = (const float*)d_in[7];
    const float* fc1_w  = (const float*)d_in[8];
    const float* fc1_b  = (const float*)d_in[9];
    const float* fc2_w  = (const float*)d_in[10];
    const float* fc2_b  = (const float*)d_in[11];
    const float* ln1_g  = (const float*)d_in[12];
    const float* ln1_b  = (const float*)d_in[13];
    const float* ln2_g  = (const float*)d_in[14];
    const float* ln2_b  = (const float*)d_in[15];
    float* out = (float*)d_out;

    float *p_ln, *p_qkv, *p_ctx, *p_x1, *p_ffn;
    cudaGetSymbolAddress((void**)&p_ln,   g_ln);
    cudaGetSymbolAddress((void**)&p_qkv,  g_qkv);
    cudaGetSymbolAddress((void**)&p_ctx,  g_ctx);
    cudaGetSymbolAddress((void**)&p_x1,   g_x1);
    cudaGetSymbolAddress((void**)&p_ffn,  g_ffn);

    const int SMG = 3 * 8192 * 4;                             // 98304
    const int SMF = (128 * KSPAD + 80 * VSPAD) * 4;           // 85248
    cudaFuncSetAttribute(mma_gemm<0>, cudaFuncAttributeMaxDynamicSharedMemorySize, SMG);
    cudaFuncSetAttribute(mma_gemm<1>, cudaFuncAttributeMaxDynamicSharedMemorySize, SMG);
    cudaFuncSetAttribute(flash_kernel, cudaFuncAttributeMaxDynamicSharedMemorySize, SMF);

    // 1. LN1
    ln_kernel<<<SS, 256>>>(x, ln1_g, ln1_b, p_ln);

    // 2. QKV = ln @ qkv_w^T + qkv_b   (4096 x 3840 x 1280)
    mma_gemm<0><<<dim3(3840 / 128, SS / 128), 128, SMG>>>(
        p_ln, HH, qkv_w, HH, p_qkv, 3 * HH,
        qkv_b, nullptr, 0, 3 * HH, HH);

    // 3. RoPE on q, k in place
    {
        int n = SS * NHEAD * (HDIM / 2);
        rope_kernel<<<(n + 255) / 256, 256>>>(p_qkv, cosp, sinp);
    }

    // 4-6. fused flash attention -> ctx
    flash_kernel<<<dim3(SS / 128, NHEAD), 256, SMF>>>(p_qkv, mask, p_ctx);

    // 7. x1 = x + ctx @ proj_w^T + proj_b
    mma_gemm<0><<<dim3(HH / 128, SS / 128), 128, SMG>>>(
        p_ctx, HH, proj_w, HH, p_x1, HH,
        proj_b, x, HH, HH, HH);

    // 8. LN2
    ln_kernel<<<SS, 256>>>(p_x1, ln2_g, ln2_b, p_ln);

    // 9. ffn = gelu(ln @ fc1_w^T + fc1_b)
    mma_gemm<1><<<dim3(IDIM / 128, SS / 128), 128, SMG>>>(
        p_ln, HH, fc1_w, HH, p_ffn, IDIM,
        fc1_b, nullptr, 0, IDIM, HH);

    // 10. out = x1 + ffn @ fc2_w^T + fc2_b
    mma_gemm<0><<<dim3(HH / 128, SS / 128), 128, SMG>>>(
        p_ffn, IDIM, fc2_w, IDIM, out, HH,
        fc2_b, p_x1, HH, HH, IDIM);
}

// round 9
// speedup vs baseline: 4.7445x; 1.3161x over previous
#include <cuda_runtime.h>
#include <math.h>
#include <stdint.h>

#define SS 4096
#define HH 1280
#define NHEAD 16
#define HDIM 80
#define IDIM 5120
#define EPSV 1e-6f

// ---------------- scratch (static device memory; no allocs allowed) --------
__device__ float g_ln  [(size_t)SS * HH];
__device__ float g_qkv [(size_t)SS * 3 * HH];
__device__ float g_ctx [(size_t)SS * HH];
__device__ float g_x1  [(size_t)SS * HH];
__device__ float g_ffn [(size_t)SS * IDIM];
// tf32-rounded weight copies
__device__ float g_wqkv[(size_t)3 * HH * HH];
__device__ float g_wproj[(size_t)HH * HH];
__device__ float g_wfc1[(size_t)IDIM * HH];
__device__ float g_wfc2[(size_t)HH * IDIM];

// ---------------- helpers ---------------------------------------------------
__device__ __forceinline__ float to_tf32(float x) {
    float r;
    asm("cvt.rna.tf32.f32 %0, %1;" : "=f"(r) : "f"(x));
    return r;
}
__device__ __forceinline__ float4 cvt4(float4 v) {
    v.x = to_tf32(v.x); v.y = to_tf32(v.y); v.z = to_tf32(v.z); v.w = to_tf32(v.w);
    return v;
}
__device__ __forceinline__ uint32_t smem_u32(const void* p) {
    uint32_t a;
    asm("{ .reg .u64 t; cvta.to.shared.u64 t, %1; cvt.u32.u64 %0, t; }" : "=r"(a) : "l"(p));
    return a;
}
__device__ __forceinline__ void mma_tf32(float* d, uint32_t a0, uint32_t a1,
                                         uint32_t a2, uint32_t a3,
                                         uint32_t b0, uint32_t b1) {
    asm volatile(
        "mma.sync.aligned.m16n8k8.row.col.f32.tf32.tf32.f32 "
        "{%0,%1,%2,%3}, {%4,%5,%6,%7}, {%8,%9}, {%0,%1,%2,%3};"
        : "+f"(d[0]), "+f"(d[1]), "+f"(d[2]), "+f"(d[3])
        : "r"(a0), "r"(a1), "r"(a2), "r"(a3), "r"(b0), "r"(b1));
}
#define CP_ASYNC16(dst, src) \
    asm volatile("cp.async.cg.shared.global [%0], [%1], 16;" :: "r"(dst), "l"(src) : "memory")
#define CP_COMMIT() asm volatile("cp.async.commit_group;" ::: "memory")
#define CP_WAIT(n)  asm volatile("cp.async.wait_group %0;" :: "n"(n) : "memory")

// ---------------- weight rounding -------------------------------------------
__global__ void round_w_kernel(const float* __restrict__ src, float* __restrict__ dst, int n4) {
    int i = blockIdx.x * blockDim.x + threadIdx.x;
    if (i < n4) ((float4*)dst)[i] = cvt4(((const float4*)src)[i]);
}

// ---------------- reductions ----------------------------------------------
__device__ __forceinline__ float block_reduce_sum(float v) {
    __shared__ float sh_sum[32];
    int lane = threadIdx.x & 31, wid = threadIdx.x >> 5;
    #pragma unroll
    for (int o = 16; o; o >>= 1) v += __shfl_xor_sync(0xffffffffu, v, o);
    if (lane == 0) sh_sum[wid] = v;
    __syncthreads();
    v = (threadIdx.x < (blockDim.x >> 5)) ? sh_sum[threadIdx.x] : 0.f;
    if (wid == 0) {
        #pragma unroll
        for (int o = 16; o; o >>= 1) v += __shfl_xor_sync(0xffffffffu, v, o);
        if (lane == 0) sh_sum[0] = v;
    }
    __syncthreads();
    float r = sh_sum[0];
    __syncthreads();
    return r;
}

// ---------------- layernorm (tf32-rounded output) ---------------------------
__global__ void ln_kernel(const float* __restrict__ x, const float* __restrict__ g,
                          const float* __restrict__ b, float* __restrict__ out) {
    int row = blockIdx.x;
    const float* xr = x + (size_t)row * HH;
    float v[5]; float s = 0.f;
    #pragma unroll
    for (int i = 0; i < 5; i++) { v[i] = xr[threadIdx.x + i * 256]; s += v[i]; }
    float mean = block_reduce_sum(s) * (1.f / HH);
    float vs = 0.f;
    #pragma unroll
    for (int i = 0; i < 5; i++) { float d = v[i] - mean; vs += d * d; }
    float var = block_reduce_sum(vs) * (1.f / HH);
    float inv = rsqrtf(var + EPSV);
    float* o = out + (size_t)row * HH;
    #pragma unroll
    for (int i = 0; i < 5; i++) {
        int c = threadIdx.x + i * 256;
        o[c] = to_tf32((v[i] - mean) * inv * g[c] + b[c]);
    }
}

// ---------------- RoPE (tf32-rounded output) --------------------------------
__global__ void rope_kernel(float* __restrict__ qkv, const float* __restrict__ cs,
                            const float* __restrict__ sn) {
    int idx = blockIdx.x * blockDim.x + threadIdx.x;
    if (idx >= SS * NHEAD * (HDIM / 2)) return;
    int d = idx % (HDIM / 2);
    int h = (idx / (HDIM / 2)) % NHEAD;
    int s = idx / ((HDIM / 2) * NHEAD);
    float c1 = cs[s * HDIM + d], c2 = cs[s * HDIM + d + 40];
    float s1 = sn[s * HDIM + d], s2 = sn[s * HDIM + d + 40];
    size_t base = (size_t)s * 3 * HH + h * HDIM;
    float* qp = qkv + base;
    float a = qp[d], bb = qp[d + 40];
    qp[d]      = to_tf32(a * c1 - bb * s1);
    qp[d + 40] = to_tf32(bb * c2 + a * s2);
    float* kp = qkv + base + HH;
    a = kp[d]; bb = kp[d + 40];
    kp[d]      = to_tf32(a * c1 - bb * s1);
    kp[d + 40] = to_tf32(bb * c2 + a * s2);
}

__device__ __forceinline__ float gelu_tanh(float x) {
    return 0.5f * x * (1.f + tanhf(0.7978845608028654f * (x + 0.044715f * x * x * x)));
}

// ================= flash attention v2 (cp.async double-buffered) ============
// grid (SS/128, NHEAD), 256 threads; warp owns 16 Q rows, full KV width.
// K tile: row-major pad 84 (frag bank (20*g4+kl)%32 conflict-free).
// V tile: row-major pad 88 (frag bank (24*kl+g4)%32 conflict-free; no transpose).
// Q/K/V values pre-rounded to tf32 by producers; cp.async loads them raw.
#define KSP 84
#define VSP 88
#define KS_STRIDE (128 * KSP)   // 10752
#define VS_STRIDE (128 * VSP)   // 11264
__global__ void __launch_bounds__(256)
flash_kernel(const float* __restrict__ qkv, const float* __restrict__ mask,
             float* __restrict__ ctx) {
    extern __shared__ float fsm[];
    float* Ks = fsm;                         // 2 x KS_STRIDE
    float* Vs = fsm + 2 * KS_STRIDE;         // 2 x VS_STRIDE
    float* Qstage = Vs + VS_STRIDE;          // aliases Vs buf1 (prologue only)
    const uint32_t smb = smem_u32(fsm);

    const int tid  = threadIdx.x;
    const int wid  = tid >> 5;
    const int lane = tid & 31;
    const int g4   = lane >> 2;
    const int kl   = lane & 3;
    const int bm   = blockIdx.x * 128;
    const int h    = blockIdx.y;
    const float scale = rsqrtf((float)HDIM);

    const float* Qb = qkv + h * HDIM;
    const float* Kb = qkv + HH + h * HDIM;
    const float* Vb = qkv + 2 * HH + h * HDIM;

    // cp.async one KV tile (128 rows x 80 floats each for K and V)
    auto issue = [&](int kv0, int b) {
        uint32_t kbase = smb + (uint32_t)(b * KS_STRIDE) * 4;
        uint32_t vbase = smb + (uint32_t)((2 * KS_STRIDE) + b * VS_STRIDE) * 4;
        #pragma unroll
        for (int i = 0; i < 10; i++) {
            int c = i * 256 + tid;
            int row = c / 20, col = (c % 20) * 4;
            CP_ASYNC16(kbase + (uint32_t)(row * KSP + col) * 4,
                       Kb + (size_t)(kv0 + row) * (3 * HH) + col);
            CP_ASYNC16(vbase + (uint32_t)(row * VSP + col) * 4,
                       Vb + (size_t)(kv0 + row) * (3 * HH) + col);
        }
        CP_COMMIT();
    };

    issue(0, 0);   // prefetch KV tile 0 (writes Ks0/Vs0; Qstage = Vs1, disjoint)

    // ---- stage Q (pre-rounded) and load fragments ----
    {
        const int lr = tid >> 1;
        const int lc = (tid & 1) * 40;
        const float* src = Qb + (size_t)(bm + lr) * (3 * HH) + lc;
        float* dst = Qstage + lr * KSP + lc;
        #pragma unroll
        for (int i = 0; i < 10; i++)
            *(float4*)(dst + i * 4) = *(const float4*)(src + i * 4);
    }
    __syncthreads();
    uint32_t qa[10][4];
    {
        int r0 = wid * 16 + g4;
        #pragma unroll
        for (int ks = 0; ks < 10; ks++) {
            qa[ks][0] = __float_as_uint(Qstage[r0 * KSP + ks * 8 + kl]);
            qa[ks][1] = __float_as_uint(Qstage[(r0 + 8) * KSP + ks * 8 + kl]);
            qa[ks][2] = __float_as_uint(Qstage[r0 * KSP + ks * 8 + kl + 4]);
            qa[ks][3] = __float_as_uint(Qstage[(r0 + 8) * KSP + ks * 8 + kl + 4]);
        }
    }

    float Oa[10][4];
    #pragma unroll
    for (int i = 0; i < 10; i++)
        #pragma unroll
        for (int j = 0; j < 4; j++) Oa[i][j] = 0.f;
    float m0 = -INFINITY, m1 = -INFINITY, l0 = 0.f, l1 = 0.f;

    const float* mrow0 = mask + (size_t)(bm + wid * 16 + g4) * SS;
    const float* mrow1 = mrow0 + (size_t)8 * SS;

    const int src_lo = (lane & ~3) | (kl >> 1);
    const int src_hi = src_lo + 2;

    constexpr int NT = SS / 128;   // 32 KV tiles
    for (int s = 0; s < NT; s++) {
        const int buf = s & 1;
        const int kv0 = s * 128;
        __syncthreads();                       // prev readers of buf^1 done
        if (s + 1 < NT) issue((s + 1) * 128, buf ^ 1);
        if (s + 1 < NT) { CP_WAIT(1); } else { CP_WAIT(0); }
        __syncthreads();                       // tile s visible to all warps

        const float* K_ = Ks + buf * KS_STRIDE;
        const float* V_ = Vs + buf * VS_STRIDE;

        // ---- S = Q K^T ----
        float sa[16][4];
        #pragma unroll
        for (int nt = 0; nt < 16; nt++)
            #pragma unroll
            for (int j = 0; j < 4; j++) sa[nt][j] = 0.f;
        #pragma unroll
        for (int ks = 0; ks < 10; ks++) {
            #pragma unroll
            for (int nt = 0; nt < 16; nt++) {
                uint32_t b0 = __float_as_uint(K_[(nt * 8 + g4) * KSP + ks * 8 + kl]);
                uint32_t b1 = __float_as_uint(K_[(nt * 8 + g4) * KSP + ks * 8 + kl + 4]);
                mma_tf32(sa[nt], qa[ks][0], qa[ks][1], qa[ks][2], qa[ks][3], b0, b1);
            }
        }

        // ---- scale + mask + row max ----
        float tmx0 = -INFINITY, tmx1 = -INFINITY;
        #pragma unroll
        for (int nt = 0; nt < 16; nt++) {
            float2 mk0 = *(const float2*)(mrow0 + kv0 + nt * 8 + 2 * kl);
            float2 mk1 = *(const float2*)(mrow1 + kv0 + nt * 8 + 2 * kl);
            sa[nt][0] = sa[nt][0] * scale + mk0.x;
            sa[nt][1] = sa[nt][1] * scale + mk0.y;
            sa[nt][2] = sa[nt][2] * scale + mk1.x;
            sa[nt][3] = sa[nt][3] * scale + mk1.y;
            tmx0 = fmaxf(tmx0, fmaxf(sa[nt][0], sa[nt][1]));
            tmx1 = fmaxf(tmx1, fmaxf(sa[nt][2], sa[nt][3]));
        }
        tmx0 = fmaxf(tmx0, __shfl_xor_sync(0xffffffffu, tmx0, 1));
        tmx0 = fmaxf(tmx0, __shfl_xor_sync(0xffffffffu, tmx0, 2));
        tmx1 = fmaxf(tmx1, __shfl_xor_sync(0xffffffffu, tmx1, 1));
        tmx1 = fmaxf(tmx1, __shfl_xor_sync(0xffffffffu, tmx1, 2));

        float nm0 = fmaxf(m0, tmx0), nm1 = fmaxf(m1, tmx1);
        float f0 = __expf(m0 - nm0), f1 = __expf(m1 - nm1);
        m0 = nm0; m1 = nm1;

        // ---- exp + row sum ----
        float ts0 = 0.f, ts1 = 0.f;
        #pragma unroll
        for (int nt = 0; nt < 16; nt++) {
            sa[nt][0] = __expf(sa[nt][0] - nm0);
            sa[nt][1] = __expf(sa[nt][1] - nm0);
            sa[nt][2] = __expf(sa[nt][2] - nm1);
            sa[nt][3] = __expf(sa[nt][3] - nm1);
            ts0 += sa[nt][0] + sa[nt][1];
            ts1 += sa[nt][2] + sa[nt][3];
        }
        ts0 += __shfl_xor_sync(0xffffffffu, ts0, 1);
        ts0 += __shfl_xor_sync(0xffffffffu, ts0, 2);
        ts1 += __shfl_xor_sync(0xffffffffu, ts1, 1);
        ts1 += __shfl_xor_sync(0xffffffffu, ts1, 2);
        l0 = l0 * f0 + ts0;
        l1 = l1 * f1 + ts1;

        // ---- rescale O ----
        #pragma unroll
        for (int no = 0; no < 10; no++) {
            Oa[no][0] *= f0; Oa[no][1] *= f0;
            Oa[no][2] *= f1; Oa[no][3] *= f1;
        }

        // ---- P -> A-frags (shuffles), O += P * V ----
        #pragma unroll
        for (int nt = 0; nt < 16; nt++) {
            float p0 = to_tf32(sa[nt][0]), p1 = to_tf32(sa[nt][1]);
            float p2 = to_tf32(sa[nt][2]), p3 = to_tf32(sa[nt][3]);
            float a0l = __shfl_sync(0xffffffffu, p0, src_lo);
            float a0h = __shfl_sync(0xffffffffu, p1, src_lo);
            float a1l = __shfl_sync(0xffffffffu, p2, src_lo);
            float a1h = __shfl_sync(0xffffffffu, p3, src_lo);
            float a2l = __shfl_sync(0xffffffffu, p0, src_hi);
            float a2h = __shfl_sync(0xffffffffu, p1, src_hi);
            float a3l = __shfl_sync(0xffffffffu, p2, src_hi);
            float a3h = __shfl_sync(0xffffffffu, p3, src_hi);
            bool odd = (kl & 1);
            uint32_t A0 = __float_as_uint(odd ? a0h : a0l);
            uint32_t A1 = __float_as_uint(odd ? a1h : a1l);
            uint32_t A2 = __float_as_uint(odd ? a2h : a2l);
            uint32_t A3 = __float_as_uint(odd ? a3h : a3l);
            #pragma unroll
            for (int no = 0; no < 10; no++) {
                uint32_t b0 = __float_as_uint(V_[(nt * 8 + kl) * VSP + no * 8 + g4]);
                uint32_t b1 = __float_as_uint(V_[(nt * 8 + kl + 4) * VSP + no * 8 + g4]);
                mma_tf32(Oa[no], A0, A1, A2, A3, b0, b1);
            }
        }
    }

    // ---- epilogue: O / l -> ctx (tf32-rounded: proj GEMM A operand) ----
    float i0 = 1.f / l0, i1 = 1.f / l1;
    int r0 = bm + wid * 16 + g4;
    float* c0p = ctx + (size_t)r0 * HH + h * HDIM;
    float* c1p = c0p + (size_t)8 * HH;
    #pragma unroll
    for (int no = 0; no < 10; no++) {
        *(float2*)(c0p + no * 8 + 2 * kl) =
            make_float2(to_tf32(Oa[no][0] * i0), to_tf32(Oa[no][1] * i0));
        *(float2*)(c1p + no * 8 + 2 * kl) =
            make_float2(to_tf32(Oa[no][2] * i1), to_tf32(Oa[no][3] * i1));
    }
}

// ================= TF32 GEMM v3: cp.async 3-stage, 64x64 warp tile ==========
// Inputs pre-rounded to tf32 -> HW truncation is exact.
// OUTR: round output to tf32 (when consumed by a later GEMM).
template<int ACT, int OUTR>
__global__ void __launch_bounds__(128)
mma_gemm(const float* __restrict__ A, int lda,
         const float* __restrict__ B, int ldb,
         float* __restrict__ C, int ldc,
         const float* __restrict__ bias,
         const float* __restrict__ Rsd, int ldr,
         int N, int K) {
    extern __shared__ float sm[];           // 3 stages x 8192 floats
    const uint32_t smb = smem_u32(sm);

    const int tid = threadIdx.x;
    const int wid = tid >> 5;
    const int lane = tid & 31;
    const int g4 = lane >> 2;
    const int kl = lane & 3;
    const int warpM = (wid >> 1) * 64;
    const int warpN = (wid & 1) * 64;
    const int bm = blockIdx.y * 128;
    const int bn = blockIdx.x * 128;

    float acc[4][8][4];
    #pragma unroll
    for (int i = 0; i < 4; i++)
        #pragma unroll
        for (int j = 0; j < 8; j++)
            #pragma unroll
            for (int q = 0; q < 4; q++) acc[i][j][q] = 0.f;

    auto issue = [&](int k0, int st) {
        uint32_t ab = smb + st * 32768;
        uint32_t bb = ab + 16384;
        #pragma unroll
        for (int i = 0; i < 8; i++) {
            int idx = i * 128 + tid;
            int row = idx >> 3, col = idx & 7;
            uint32_t sw = (uint32_t)((col ^ (row & 7)) << 4);
            CP_ASYNC16(ab + row * 128 + sw, A + (size_t)(bm + row) * lda + k0 + col * 4);
            CP_ASYNC16(bb + row * 128 + sw, B + (size_t)(bn + row) * ldb + k0 + col * 4);
        }
        CP_COMMIT();
    };

    auto compute = [&](int st) {
        const float* As = sm + st * 8192;
        const float* Bs = As + 4096;
        #pragma unroll
        for (int ko = 0; ko < 4; ko++) {
            const int cc0 = (((ko * 2)     ^ g4) << 2) | kl;
            const int cc1 = (((ko * 2 + 1) ^ g4) << 2) | kl;
            uint32_t af[4][4], bf[8][2];
            #pragma unroll
            for (int mt = 0; mt < 4; mt++) {
                int m = warpM + mt * 16 + g4;
                af[mt][0] = __float_as_uint(As[m * 32 + cc0]);
                af[mt][1] = __float_as_uint(As[(m + 8) * 32 + cc0]);
                af[mt][2] = __float_as_uint(As[m * 32 + cc1]);
                af[mt][3] = __float_as_uint(As[(m + 8) * 32 + cc1]);
            }
            #pragma unroll
            for (int nt = 0; nt < 8; nt++) {
                int n = warpN + nt * 8 + g4;
                bf[nt][0] = __float_as_uint(Bs[n * 32 + cc0]);
                bf[nt][1] = __float_as_uint(Bs[n * 32 + cc1]);
            }
            #pragma unroll
            for (int mt = 0; mt < 4; mt++)
                #pragma unroll
                for (int nt = 0; nt < 8; nt++)
                    mma_tf32(acc[mt][nt], af[mt][0], af[mt][1], af[mt][2], af[mt][3],
                             bf[nt][0], bf[nt][1]);
        }
    };

    const int nst = K / 32;
    issue(0, 0);
    if (nst > 1) issue(32, 1);
    int st = 0;
    for (int s = 0; s < nst; s++) {
        if (s + 1 < nst) { CP_WAIT(1); } else { CP_WAIT(0); }
        __syncthreads();
        if (s + 2 < nst) {
            int st2 = st + 2; if (st2 >= 3) st2 -= 3;
            issue((s + 2) * 32, st2);
        }
        compute(st);
        if (++st == 3) st = 0;
    }

    // ---- epilogue ----
    #pragma unroll
    for (int mt = 0; mt < 4; mt++) {
        #pragma unroll
        for (int rr = 0; rr < 2; rr++) {
            int r_ = bm + warpM + mt * 16 + g4 + rr * 8;
            float* Crow = C + (size_t)r_ * ldc;
            const float* Rrow = Rsd ? (Rsd + (size_t)r_ * ldr) : nullptr;
            #pragma unroll
            for (int nt = 0; nt < 8; nt++) {
                int col = bn + warpN + nt * 8 + kl * 2;
                float v0 = acc[mt][nt][rr * 2 + 0];
                float v1 = acc[mt][nt][rr * 2 + 1];
                if (bias) { v0 += bias[col]; v1 += bias[col + 1]; }
                if (ACT == 1) { v0 = gelu_tanh(v0); v1 = gelu_tanh(v1); }
                if (Rrow) { v0 += Rrow[col]; v1 += Rrow[col + 1]; }
                if (OUTR) { v0 = to_tf32(v0); v1 = to_tf32(v1); }
                *(float2*)(Crow + col) = make_float2(v0, v1);
            }
        }
    }
}

// ---------------- launch ----------------------------------------------------
extern "C" void kernel_launch(void* const* d_in, const int* in_sizes, int n_in,
                              void* d_out, int out_size) {
    const float* x      = (const float*)d_in[0];
    const float* mask   = (const float*)d_in[1];
    const float* cosp   = (const float*)d_in[2];
    const float* sinp   = (const float*)d_in[3];
    const float* qkv_w  = (const float*)d_in[4];
    const float* qkv_b  = (const float*)d_in[5];
    const float* proj_w = (const float*)d_in[6];
    const float* proj_b = (const float*)d_in[7];
    const float* fc1_w  = (const float*)d_in[8];
    const float* fc1_b  = (const float*)d_in[9];
    const float* fc2_w  = (const float*)d_in[10];
    const float* fc2_b  = (const float*)d_in[11];
    const float* ln1_g  = (const float*)d_in[12];
    const float* ln1_b  = (const float*)d_in[13];
    const float* ln2_g  = (const float*)d_in[14];
    const float* ln2_b  = (const float*)d_in[15];
    float* out = (float*)d_out;

    float *p_ln, *p_qkv, *p_ctx, *p_x1, *p_ffn;
    float *p_wqkv, *p_wproj, *p_wfc1, *p_wfc2;
    cudaGetSymbolAddress((void**)&p_ln,   g_ln);
    cudaGetSymbolAddress((void**)&p_qkv,  g_qkv);
    cudaGetSymbolAddress((void**)&p_ctx,  g_ctx);
    cudaGetSymbolAddress((void**)&p_x1,   g_x1);
    cudaGetSymbolAddress((void**)&p_ffn,  g_ffn);
    cudaGetSymbolAddress((void**)&p_wqkv, g_wqkv);
    cudaGetSymbolAddress((void**)&p_wproj,g_wproj);
    cudaGetSymbolAddress((void**)&p_wfc1, g_wfc1);
    cudaGetSymbolAddress((void**)&p_wfc2, g_wfc2);

    const int SMG = 3 * 8192 * 4;                                   // 98304
    const int SMF = (2 * KS_STRIDE + 2 * VS_STRIDE) * 4;            // 176128
    cudaFuncSetAttribute(mma_gemm<0, 0>, cudaFuncAttributeMaxDynamicSharedMemorySize, SMG);
    cudaFuncSetAttribute(mma_gemm<0, 1>, cudaFuncAttributeMaxDynamicSharedMemorySize, SMG);
    cudaFuncSetAttribute(mma_gemm<1, 1>, cudaFuncAttributeMaxDynamicSharedMemorySize, SMG);
    cudaFuncSetAttribute(flash_kernel, cudaFuncAttributeMaxDynamicSharedMemorySize, SMF);

    // 0. round weights to tf32 (makes GEMM truncation exact)
    {
        int n;
        n = 3 * HH * HH / 4;  round_w_kernel<<<(n + 255) / 256, 256>>>(qkv_w,  p_wqkv,  n);
        n = HH * HH / 4;      round_w_kernel<<<(n + 255) / 256, 256>>>(proj_w, p_wproj, n);
        n = IDIM * HH / 4;    round_w_kernel<<<(n + 255) / 256, 256>>>(fc1_w,  p_wfc1,  n);
        n = HH * IDIM / 4;    round_w_kernel<<<(n + 255) / 256, 256>>>(fc2_w,  p_wfc2,  n);
    }

    // 1. LN1 (rounded output)
    ln_kernel<<<SS, 256>>>(x, ln1_g, ln1_b, p_ln);

    // 2. QKV = ln @ qkv_w^T + qkv_b  (rounded output: feeds flash V, rope)
    mma_gemm<0, 1><<<dim3(3840 / 128, SS / 128), 128, SMG>>>(
        p_ln, HH, p_wqkv, HH, p_qkv, 3 * HH,
        qkv_b, nullptr, 0, 3 * HH, HH);

    // 3. RoPE on q, k in place (rounded output)
    {
        int n = SS * NHEAD * (HDIM / 2);
        rope_kernel<<<(n + 255) / 256, 256>>>(p_qkv, cosp, sinp);
    }

    // 4-6. fused flash attention -> ctx (rounded output)
    flash_kernel<<<dim3(SS / 128, NHEAD), 256, SMF>>>(p_qkv, mask, p_ctx);

    // 7. x1 = x + ctx @ proj_w^T + proj_b  (fp32: residual stream)
    mma_gemm<0, 0><<<dim3(HH / 128, SS / 128), 128, SMG>>>(
        p_ctx, HH, p_wproj, HH, p_x1, HH,
        proj_b, x, HH, HH, HH);

    // 8. LN2 (rounded output)
    ln_kernel<<<SS, 256>>>(p_x1, ln2_g, ln2_b, p_ln);

    // 9. ffn = gelu(ln @ fc1_w^T + fc1_b)  (rounded output)
    mma_gemm<1, 1><<<dim3(IDIM / 128, SS / 128), 128, SMG>>>(
        p_ln, HH, p_wfc1, HH, p_ffn, IDIM,
        fc1_b, nullptr, 0, IDIM, HH);

    // 10. out = x1 + ffn @ fc2_w^T + fc2_b  (fp32: final output)
    mma_gemm<0, 0><<<dim3(HH / 128, SS / 128), 128, SMG>>>(
        p_ffn, IDIM, p_wfc2, IDIM, out, HH,
        fc2_b, p_x1, HH, HH, IDIM);
}